// round 3
// baseline (speedup 1.0000x reference)
#include <cuda_runtime.h>
#include <cuda_bf16.h>
#include <cstdint>

#define ND 50000
#define NG 100000
#define NE 600000

// ---------------- static scratch ----------------
__device__ __align__(16) float g_td[(size_t)ND * 128];
__device__ __align__(16) float g_tg[(size_t)NG * 128];
__device__ __align__(16) float g_d1[(size_t)ND * 64];
__device__ __align__(16) float g_g1[(size_t)NG * 64];
// 4 weight images: [n=128][k=K] bf16, padded rows (K+8), hi then lo. slot = 69632 B
__device__ __align__(16) char g_wimg[4 * 69632];

__device__ int g_rp_g[NG + 1];
__device__ int g_rp_d[ND + 1];
__device__ int g_cur_g[NG];
__device__ int g_cur_d[ND];
__device__ int g_col_dg[NE];
__device__ int g_col_gd[NE];
__device__ int g_bs_g[64];
__device__ int g_bs_d[64];

// ---------------- helpers ----------------
__device__ __forceinline__ uint32_t smem_u32(const void* p) {
    uint32_t a;
    asm("{ .reg .u64 t; cvta.to.shared.u64 t, %1; cvt.u32.u64 %0, t; }" : "=r"(a) : "l"(p));
    return a;
}
__device__ __forceinline__ void ldm4(uint32_t* r, uint32_t addr) {
    asm volatile("ldmatrix.sync.aligned.m8n8.x4.shared.b16 {%0,%1,%2,%3}, [%4];"
                 : "=r"(r[0]), "=r"(r[1]), "=r"(r[2]), "=r"(r[3]) : "r"(addr));
}
__device__ __forceinline__ void mma_bf16(float* c, const uint32_t* a, const uint32_t* b) {
    asm volatile(
        "mma.sync.aligned.m16n8k16.row.col.f32.bf16.bf16.f32 "
        "{%0,%1,%2,%3}, {%4,%5,%6,%7}, {%8,%9}, {%0,%1,%2,%3};"
        : "+f"(c[0]), "+f"(c[1]), "+f"(c[2]), "+f"(c[3])
        : "r"(a[0]), "r"(a[1]), "r"(a[2]), "r"(a[3]), "r"(b[0]), "r"(b[1]));
}

// ---------------- weight image prep ----------------
// image[n][k] = W[k][n'] (dual concat: n<64 -> Wa, else Wb), bf16 hi/lo, row stride K+8
__global__ void prep_w_kernel(const float* __restrict__ Wa0, const float* __restrict__ Wb0,
                              const float* __restrict__ Wa1, const float* __restrict__ Wb1,
                              const float* __restrict__ Wa2, const float* __restrict__ Wb2,
                              const float* __restrict__ Wa3, const float* __restrict__ Wb3) {
    int img = blockIdx.x;
    const float *Wa, *Wb;
    int K;
    if (img == 0) { Wa = Wa0; Wb = Wb0; K = 128; }
    else if (img == 1) { Wa = Wa1; Wb = Wb1; K = 128; }
    else if (img == 2) { Wa = Wa2; Wb = Wb2; K = 64; }
    else { Wa = Wa3; Wb = Wb3; K = 64; }
    int rowb = (K + 8) * 2;
    char* hi_img = g_wimg + (size_t)img * 69632;
    char* lo_img = hi_img + 128 * rowb;
    for (int i = threadIdx.x; i < 128 * K; i += blockDim.x) {
        int n = i / K, k = i % K;
        float w = (n < 64) ? Wa[k * 64 + n] : Wb[k * 64 + (n - 64)];
        __nv_bfloat16 h = __float2bfloat16(w);
        __nv_bfloat16 l = __float2bfloat16(w - __bfloat162float(h));
        *(__nv_bfloat16*)(hi_img + n * rowb + k * 2) = h;
        *(__nv_bfloat16*)(lo_img + n * rowb + k * 2) = l;
    }
}

// ---------------- HMMA GEMM: out[N,128] = X[N,K] @ W (bf16 hi/lo x3) ----------------
// CTA: 256 thr (8 warps, 4m x 2n), tile 128x128.
template <int K>
__global__ __launch_bounds__(256) void gemm_mma(
    const float* __restrict__ Xd, const float* __restrict__ Xg,
    float* __restrict__ outd, float* __restrict__ outg,
    int img_d, int img_g, int Ndis, int Ngen, int tilesD) {
    constexpr int STR = K + 8;            // bf16 per row
    constexpr int ROWB = STR * 2;         // bytes per row
    constexpr int MAT = 128 * ROWB;       // one matrix (hi or lo) bytes
    constexpr int NSTEP = K / 16;
    extern __shared__ __align__(16) char smem[];
    char* Ahi = smem;                     // [128][STR]
    char* Bhi = smem + 2 * MAT;           // Alo = Ahi+MAT, Blo = Bhi+MAT

    const int tid = threadIdx.x;
    const float* X;
    float* out;
    int Nrows, img, tb = blockIdx.x;
    if (tb < tilesD) { X = Xd; out = outd; Nrows = Ndis; img = img_d; }
    else { tb -= tilesD; X = Xg; out = outg; Nrows = Ngen; img = img_g; }
    const int row0 = tb * 128;

    // A: load 128 x K fp32, split bf16 hi/lo, store padded row-major
    for (int v = tid; v < 128 * (K / 4); v += 256) {
        int m = v / (K / 4);
        int k = (v % (K / 4)) * 4;
        int gr = row0 + m;
        float4 x = make_float4(0.f, 0.f, 0.f, 0.f);
        if (gr < Nrows) x = *(const float4*)(X + (size_t)gr * K + k);
        __nv_bfloat16 h0 = __float2bfloat16(x.x), h1 = __float2bfloat16(x.y);
        __nv_bfloat16 h2 = __float2bfloat16(x.z), h3 = __float2bfloat16(x.w);
        __nv_bfloat16 l0 = __float2bfloat16(x.x - __bfloat162float(h0));
        __nv_bfloat16 l1 = __float2bfloat16(x.y - __bfloat162float(h1));
        __nv_bfloat16 l2 = __float2bfloat16(x.z - __bfloat162float(h2));
        __nv_bfloat16 l3 = __float2bfloat16(x.w - __bfloat162float(h3));
        uint2 hv, lv;
        hv.x = (uint32_t)__bfloat16_as_ushort(h0) | ((uint32_t)__bfloat16_as_ushort(h1) << 16);
        hv.y = (uint32_t)__bfloat16_as_ushort(h2) | ((uint32_t)__bfloat16_as_ushort(h3) << 16);
        lv.x = (uint32_t)__bfloat16_as_ushort(l0) | ((uint32_t)__bfloat16_as_ushort(l1) << 16);
        lv.y = (uint32_t)__bfloat16_as_ushort(l2) | ((uint32_t)__bfloat16_as_ushort(l3) << 16);
        uint32_t off = (uint32_t)(m * ROWB + k * 2);
        *(uint2*)(Ahi + off) = hv;
        *(uint2*)(Ahi + MAT + off) = lv;
    }
    // B: linear copy of pre-padded image (hi + lo)
    {
        const char* im = g_wimg + (size_t)img * 69632;
        for (int v = tid; v < (2 * MAT) / 16; v += 256)
            *(float4*)(Bhi + v * 16) = *(const float4*)(im + v * 16);
    }
    __syncthreads();

    const int w = tid >> 5, lane = tid & 31;
    const int mw = w >> 1, nw = w & 1;
    const int g = lane >> 2, t = lane & 3;

    // ldmatrix lane base addresses
    uint32_t aB = smem_u32(Ahi) + (uint32_t)((mw * 32 + (lane & 15)) * ROWB + (lane >> 4) * 16);
    uint32_t bB = smem_u32(Bhi) +
                  (uint32_t)((nw * 64 + ((lane >> 4) << 3) + (lane & 7)) * ROWB +
                             ((lane >> 3) & 1) * 16);

    float c[2][8][4];
#pragma unroll
    for (int a = 0; a < 2; a++)
#pragma unroll
        for (int b = 0; b < 8; b++)
#pragma unroll
            for (int q = 0; q < 4; q++) c[a][b][q] = 0.f;

#pragma unroll
    for (int s = 0; s < NSTEP; s++) {
        const uint32_t ko = (uint32_t)(s * 32);
        uint32_t ah0[4], ah1[4], al0[4], al1[4];
        ldm4(ah0, aB + ko);
        ldm4(ah1, aB + 16 * ROWB + ko);
        ldm4(al0, aB + MAT + ko);
        ldm4(al1, aB + MAT + 16 * ROWB + ko);
#pragma unroll
        for (int p = 0; p < 4; p++) {
            uint32_t bh[4], bl[4];
            ldm4(bh, bB + p * 16 * ROWB + ko);
            ldm4(bl, bB + MAT + p * 16 * ROWB + ko);
#pragma unroll
            for (int q = 0; q < 2; q++) {
                int j = 2 * p + q;
                mma_bf16(c[0][j], ah0, bh + 2 * q);
                mma_bf16(c[0][j], ah0, bl + 2 * q);
                mma_bf16(c[0][j], al0, bh + 2 * q);
                mma_bf16(c[1][j], ah1, bh + 2 * q);
                mma_bf16(c[1][j], ah1, bl + 2 * q);
                mma_bf16(c[1][j], al1, bh + 2 * q);
            }
        }
    }
    __syncthreads();

    // stage D in smem (stride 132 floats), then coalesced float4 stores
    float* ds = (float*)smem;
#pragma unroll
    for (int mt = 0; mt < 2; mt++) {
#pragma unroll
        for (int j = 0; j < 8; j++) {
            int r = mw * 32 + mt * 16 + g;
            int col = nw * 64 + j * 8 + 2 * t;
            ds[r * 132 + col] = c[mt][j][0];
            ds[r * 132 + col + 1] = c[mt][j][1];
            ds[(r + 8) * 132 + col] = c[mt][j][2];
            ds[(r + 8) * 132 + col + 1] = c[mt][j][3];
        }
    }
    __syncthreads();
    for (int i = tid; i < 128 * 32; i += 256) {
        int mm = i >> 5, cq = (i & 31) * 4;
        int gr = row0 + mm;
        if (gr < Nrows) *(float4*)(out + (size_t)gr * 128 + cq) = *(float4*)(&ds[mm * 132 + cq]);
    }
}

// ---------------- CSR build ----------------
__global__ void zero_counts_kernel() {
    int i = blockIdx.x * blockDim.x + threadIdx.x;
    if (i < NG) g_cur_g[i] = 0;
    if (i < ND) g_cur_d[i] = 0;
}
__global__ void hist_kernel(const int* __restrict__ dst, int e, int* __restrict__ cnt) {
    int i = blockIdx.x * blockDim.x + threadIdx.x;
    if (i < e) atomicAdd(&cnt[dst[i]], 1);
}
__global__ void scan_block_sums(const int* __restrict__ cnt, int n, int* __restrict__ bsums) {
    __shared__ int sdata[256];
    int tid = threadIdx.x;
    int base = blockIdx.x * 2048;
    int s = 0;
    for (int i = tid; i < 2048; i += 256) {
        int idx = base + i;
        if (idx < n) s += cnt[idx];
    }
    sdata[tid] = s;
    __syncthreads();
    for (int o = 128; o > 0; o >>= 1) {
        if (tid < o) sdata[tid] += sdata[tid + o];
        __syncthreads();
    }
    if (tid == 0) bsums[blockIdx.x] = sdata[0];
}
__global__ void scan_small(int* __restrict__ bs, int nb) {
    __shared__ int s[64];
    int tid = threadIdx.x;
    int orig = (tid < nb) ? bs[tid] : 0;
    s[tid] = orig;
    __syncthreads();
    for (int o = 1; o < 64; o <<= 1) {
        int v = (tid >= o) ? s[tid - o] : 0;
        __syncthreads();
        s[tid] += v;
        __syncthreads();
    }
    if (tid < nb) bs[tid] = s[tid] - orig;
}
__global__ void scan_finalize(const int* __restrict__ cnt, int n,
                              const int* __restrict__ bsums,
                              int* __restrict__ row_ptr, int* __restrict__ cursor) {
    __shared__ int sh[256];
    int tid = threadIdx.x;
    int base = blockIdx.x * 2048 + tid * 8;
    int v[8];
    int tsum = 0;
#pragma unroll
    for (int i = 0; i < 8; i++) {
        int idx = base + i;
        v[i] = (idx < n) ? cnt[idx] : 0;
        tsum += v[i];
    }
    sh[tid] = tsum;
    __syncthreads();
    for (int o = 1; o < 256; o <<= 1) {
        int add = (tid >= o) ? sh[tid - o] : 0;
        __syncthreads();
        sh[tid] += add;
        __syncthreads();
    }
    int run = sh[tid] - tsum + bsums[blockIdx.x];
#pragma unroll
    for (int i = 0; i < 8; i++) {
        int idx = base + i;
        if (idx < n) {
            cursor[idx] = run;
            run += v[i];
            row_ptr[idx + 1] = run;
        }
    }
    if (blockIdx.x == 0 && tid == 0) row_ptr[0] = 0;
}
__global__ void scatter_kernel(const int* __restrict__ src, const int* __restrict__ dst,
                               int e, int* __restrict__ cursor, int* __restrict__ col) {
    int i = blockIdx.x * blockDim.x + threadIdx.x;
    if (i < e) {
        int p = atomicAdd(&cursor[dst[i]], 1);
        col[p] = src[i];
    }
}

// ---------------- CSR mean-aggregate + bias + self ----------------
__global__ void aggregate_kernel(const float* __restrict__ tsrc,
                                 const float* __restrict__ tself,
                                 const float* __restrict__ bias,
                                 const int* __restrict__ rp,
                                 const int* __restrict__ col,
                                 float* __restrict__ out, int n_dst) {
    int t = blockIdx.x * blockDim.x + threadIdx.x;
    int n = t >> 6;
    int d = t & 63;
    if (n >= n_dst) return;
    int beg = rp[n], end = rp[n + 1];
    float acc = 0.f;
    for (int e = beg; e < end; e++) {
        acc += __ldg(&tsrc[(size_t)col[e] * 128 + d]);
    }
    float inv = (end > beg) ? 1.f / (float)(end - beg) : 0.f;
    out[(size_t)n * 64 + d] = acc * inv + bias[d] + tself[(size_t)n * 128 + 64 + d];
}

// ---------------- host launcher ----------------
extern "C" void kernel_launch(void* const* d_in, const int* in_sizes, int n_in,
                              void* d_out, int out_size) {
    const float* x_d = (const float*)d_in[0];
    const float* x_g = (const float*)d_in[1];
    const int* src_dg = (const int*)d_in[2];
    const int* dst_dg = (const int*)d_in[3];
    const int* src_gd = (const int*)d_in[4];
    const int* dst_gd = (const int*)d_in[5];
    const float* Wl1_dg = (const float*)d_in[6];
    const float* bl1_dg = (const float*)d_in[7];
    const float* Wr1_dg = (const float*)d_in[8];
    const float* Wl1_gd = (const float*)d_in[9];
    const float* bl1_gd = (const float*)d_in[10];
    const float* Wr1_gd = (const float*)d_in[11];
    const float* Wl2_dg = (const float*)d_in[12];
    const float* bl2_dg = (const float*)d_in[13];
    const float* Wr2_dg = (const float*)d_in[14];
    const float* Wl2_gd = (const float*)d_in[15];
    const float* bl2_gd = (const float*)d_in[16];
    const float* Wr2_gd = (const float*)d_in[17];
    float* out = (float*)d_out;

    int E = in_sizes[2];
    if (E > NE) E = NE;

    float *td, *tg, *d1, *g1;
    int *rpg, *rpd, *curg, *curd, *coldg, *colgd, *bsg, *bsd;
    cudaGetSymbolAddress((void**)&td, g_td);
    cudaGetSymbolAddress((void**)&tg, g_tg);
    cudaGetSymbolAddress((void**)&d1, g_d1);
    cudaGetSymbolAddress((void**)&g1, g_g1);
    cudaGetSymbolAddress((void**)&rpg, g_rp_g);
    cudaGetSymbolAddress((void**)&rpd, g_rp_d);
    cudaGetSymbolAddress((void**)&curg, g_cur_g);
    cudaGetSymbolAddress((void**)&curd, g_cur_d);
    cudaGetSymbolAddress((void**)&coldg, g_col_dg);
    cudaGetSymbolAddress((void**)&colgd, g_col_gd);
    cudaGetSymbolAddress((void**)&bsg, g_bs_g);
    cudaGetSymbolAddress((void**)&bsd, g_bs_d);

    const int tilesD = (ND + 127) / 128;   // 391
    const int tilesG = (NG + 127) / 128;   // 782
    const int dsz128 = 4 * 128 * (128 + 8) * 2;   // 139264
    const int dsz64 = 4 * 128 * (64 + 8) * 2;     // 73728
    cudaFuncSetAttribute(gemm_mma<128>, cudaFuncAttributeMaxDynamicSharedMemorySize, dsz128);
    cudaFuncSetAttribute(gemm_mma<64>, cudaFuncAttributeMaxDynamicSharedMemorySize, dsz64);

    const int nb_g = (NG + 2047) / 2048;
    const int nb_d = (ND + 2047) / 2048;
    const int eblocks = (E + 255) / 256;

    // order chosen so ncu -s 5 -c 1 captures the layer-1 tensor GEMM (launch #6)
    prep_w_kernel<<<4, 256>>>(Wl1_dg, Wr1_gd, Wl1_gd, Wr1_dg,
                              Wl2_dg, Wr2_gd, Wl2_gd, Wr2_dg);        // 1
    zero_counts_kernel<<<(NG + 255) / 256, 256>>>();                  // 2
    hist_kernel<<<eblocks, 256>>>(dst_dg, E, curg);                   // 3
    hist_kernel<<<eblocks, 256>>>(dst_gd, E, curd);                   // 4
    scan_block_sums<<<nb_g, 256>>>(curg, NG, bsg);                    // 5
    gemm_mma<128><<<tilesD + tilesG, 256, dsz128>>>(x_d, x_g, td, tg,
                                                    0, 1, ND, NG, tilesD);  // 6 (profiled)
    scan_small<<<1, 64>>>(bsg, nb_g);                                 // 7
    scan_finalize<<<nb_g, 256>>>(curg, NG, bsg, rpg, curg);           // 8
    scan_block_sums<<<nb_d, 256>>>(curd, ND, bsd);                    // 9
    scan_small<<<1, 64>>>(bsd, nb_d);                                 // 10
    scan_finalize<<<nb_d, 256>>>(curd, ND, bsd, rpd, curd);           // 11
    scatter_kernel<<<eblocks, 256>>>(src_dg, dst_dg, E, curg, coldg); // 12
    scatter_kernel<<<eblocks, 256>>>(src_gd, dst_gd, E, curd, colgd); // 13

    aggregate_kernel<<<(NG * 64 + 255) / 256, 256>>>(td, tg, bl1_dg, rpg, coldg, g1, NG);
    aggregate_kernel<<<(ND * 64 + 255) / 256, 256>>>(tg, td, bl1_gd, rpd, colgd, d1, ND);

    gemm_mma<64><<<tilesD + tilesG, 256, dsz64>>>(d1, g1, td, tg, 2, 3, ND, NG, tilesD);

    aggregate_kernel<<<(NG * 64 + 255) / 256, 256>>>(td, tg, bl2_dg, rpg, coldg,
                                                     out + (size_t)ND * 64, NG);
    aggregate_kernel<<<(ND * 64 + 255) / 256, 256>>>(tg, td, bl2_gd, rpd, colgd,
                                                     out, ND);
}

// round 4
// speedup vs baseline: 1.5107x; 1.5107x over previous
#include <cuda_runtime.h>
#include <cuda_bf16.h>
#include <cstdint>

#define ND 50000
#define NG 100000
#define NE 600000

// ---------------- static scratch ----------------
__device__ __align__(16) float g_a_d[(size_t)ND * 64];
__device__ __align__(16) float g_r_d[(size_t)ND * 64];
__device__ __align__(16) float g_a_g[(size_t)NG * 64];
__device__ __align__(16) float g_r_g[(size_t)NG * 64];
__device__ __align__(16) float g_d1[(size_t)ND * 64];
__device__ __align__(16) float g_g1[(size_t)NG * 64];
// 4 weight images: [n=128][k=K] bf16, padded rows (K+8), hi then lo. slot = 69632 B
__device__ __align__(16) char g_wimg[4 * 69632];

__device__ int g_rp_g[NG + 1];
__device__ int g_rp_d[ND + 1];
__device__ int g_cur_g[NG];
__device__ int g_cur_d[ND];
__device__ int g_col_dg[NE];
__device__ int g_col_gd[NE];
__device__ int g_bs_g[64];
__device__ int g_bs_d[64];

// ---------------- helpers ----------------
__device__ __forceinline__ uint32_t smem_u32(const void* p) {
    uint32_t a;
    asm("{ .reg .u64 t; cvta.to.shared.u64 t, %1; cvt.u32.u64 %0, t; }" : "=r"(a) : "l"(p));
    return a;
}
__device__ __forceinline__ void ldm4(uint32_t* r, uint32_t addr) {
    asm volatile("ldmatrix.sync.aligned.m8n8.x4.shared.b16 {%0,%1,%2,%3}, [%4];"
                 : "=r"(r[0]), "=r"(r[1]), "=r"(r[2]), "=r"(r[3]) : "r"(addr));
}
__device__ __forceinline__ void mma_bf16(float* c, const uint32_t* a, const uint32_t* b) {
    asm volatile(
        "mma.sync.aligned.m16n8k16.row.col.f32.bf16.bf16.f32 "
        "{%0,%1,%2,%3}, {%4,%5,%6,%7}, {%8,%9}, {%0,%1,%2,%3};"
        : "+f"(c[0]), "+f"(c[1]), "+f"(c[2]), "+f"(c[3])
        : "r"(a[0]), "r"(a[1]), "r"(a[2]), "r"(a[3]), "r"(b[0]), "r"(b[1]));
}

// ---------------- weight image prep ----------------
__global__ void prep_w_kernel(const float* __restrict__ Wa0, const float* __restrict__ Wb0,
                              const float* __restrict__ Wa1, const float* __restrict__ Wb1,
                              const float* __restrict__ Wa2, const float* __restrict__ Wb2,
                              const float* __restrict__ Wa3, const float* __restrict__ Wb3) {
    int img = blockIdx.x;
    const float *Wa, *Wb;
    int K;
    if (img == 0) { Wa = Wa0; Wb = Wb0; K = 128; }
    else if (img == 1) { Wa = Wa1; Wb = Wb1; K = 128; }
    else if (img == 2) { Wa = Wa2; Wb = Wb2; K = 64; }
    else { Wa = Wa3; Wb = Wb3; K = 64; }
    int rowb = (K + 8) * 2;
    char* hi_img = g_wimg + (size_t)img * 69632;
    char* lo_img = hi_img + 128 * rowb;
    for (int i = threadIdx.x; i < 128 * K; i += blockDim.x) {
        int n = i / K, k = i % K;
        float w = (n < 64) ? Wa[k * 64 + n] : Wb[k * 64 + (n - 64)];
        __nv_bfloat16 h = __float2bfloat16(w);
        __nv_bfloat16 l = __float2bfloat16(w - __bfloat162float(h));
        *(__nv_bfloat16*)(hi_img + n * rowb + k * 2) = h;
        *(__nv_bfloat16*)(lo_img + n * rowb + k * 2) = l;
    }
}

// ---------------- HMMA GEMM: [a|r](N,64+64) = X[N,K] @ W, M-tile = 64 ----------------
// 256 thr (8 warps, 4m x 2n). smem: Ahi,Alo [64][K+8], Bhi,Blo [128][K+8].
template <int K>
__global__ __launch_bounds__(256) void gemm_mma(
    const float* __restrict__ Xd, const float* __restrict__ Xg,
    float* __restrict__ ad, float* __restrict__ rd,
    float* __restrict__ ag, float* __restrict__ rg,
    int img_d, int img_g, int Ndis, int Ngen, int tilesD) {
    constexpr int STR = K + 8;
    constexpr int ROWB = STR * 2;
    constexpr int AMAT = 64 * ROWB;
    constexpr int BMAT = 128 * ROWB;
    constexpr int NSTEP = K / 16;
    extern __shared__ __align__(16) char smem[];
    char* Ahi = smem;                       // [64][STR]
    char* Bhi = smem + 2 * AMAT;            // Alo = Ahi+AMAT, Blo = Bhi+BMAT

    const int tid = threadIdx.x;
    const float* X;
    float *outa, *outr;
    int Nrows, img, tb = blockIdx.x;
    if (tb < tilesD) { X = Xd; outa = ad; outr = rd; Nrows = Ndis; img = img_d; }
    else { tb -= tilesD; X = Xg; outa = ag; outr = rg; Nrows = Ngen; img = img_g; }
    const int row0 = tb * 64;

    // A: load 64 x K fp32, bf16 hi/lo split, padded row-major
    for (int v = tid; v < 64 * (K / 4); v += 256) {
        int m = v / (K / 4);
        int k = (v % (K / 4)) * 4;
        int gr = row0 + m;
        float4 x = make_float4(0.f, 0.f, 0.f, 0.f);
        if (gr < Nrows) x = *(const float4*)(X + (size_t)gr * K + k);
        __nv_bfloat16 h0 = __float2bfloat16(x.x), h1 = __float2bfloat16(x.y);
        __nv_bfloat16 h2 = __float2bfloat16(x.z), h3 = __float2bfloat16(x.w);
        __nv_bfloat16 l0 = __float2bfloat16(x.x - __bfloat162float(h0));
        __nv_bfloat16 l1 = __float2bfloat16(x.y - __bfloat162float(h1));
        __nv_bfloat16 l2 = __float2bfloat16(x.z - __bfloat162float(h2));
        __nv_bfloat16 l3 = __float2bfloat16(x.w - __bfloat162float(h3));
        uint2 hv, lv;
        hv.x = (uint32_t)__bfloat16_as_ushort(h0) | ((uint32_t)__bfloat16_as_ushort(h1) << 16);
        hv.y = (uint32_t)__bfloat16_as_ushort(h2) | ((uint32_t)__bfloat16_as_ushort(h3) << 16);
        lv.x = (uint32_t)__bfloat16_as_ushort(l0) | ((uint32_t)__bfloat16_as_ushort(l1) << 16);
        lv.y = (uint32_t)__bfloat16_as_ushort(l2) | ((uint32_t)__bfloat16_as_ushort(l3) << 16);
        uint32_t off = (uint32_t)(m * ROWB + k * 2);
        *(uint2*)(Ahi + off) = hv;
        *(uint2*)(Ahi + AMAT + off) = lv;
    }
    // B: linear copy of pre-padded image (hi + lo)
    {
        const char* im = g_wimg + (size_t)img * 69632;
        for (int v = tid; v < (2 * BMAT) / 16; v += 256)
            *(float4*)(Bhi + v * 16) = *(const float4*)(im + v * 16);
    }
    __syncthreads();

    const int w = tid >> 5, lane = tid & 31;
    const int mw = w >> 1, nw = w & 1;
    const int g = lane >> 2, t = lane & 3;

    uint32_t aB = smem_u32(Ahi) + (uint32_t)((mw * 16 + (lane & 15)) * ROWB + (lane >> 4) * 16);
    uint32_t bB = smem_u32(Bhi) +
                  (uint32_t)((nw * 64 + ((lane >> 4) << 3) + (lane & 7)) * ROWB +
                             ((lane >> 3) & 1) * 16);

    float c[8][4];
#pragma unroll
    for (int b = 0; b < 8; b++)
#pragma unroll
        for (int q = 0; q < 4; q++) c[b][q] = 0.f;

#pragma unroll
    for (int s = 0; s < NSTEP; s++) {
        const uint32_t ko = (uint32_t)(s * 32);
        uint32_t ah[4], al[4];
        ldm4(ah, aB + ko);
        ldm4(al, aB + AMAT + ko);
#pragma unroll
        for (int p = 0; p < 4; p++) {
            uint32_t bh[4], bl[4];
            ldm4(bh, bB + p * 16 * ROWB + ko);
            ldm4(bl, bB + BMAT + p * 16 * ROWB + ko);
#pragma unroll
            for (int q = 0; q < 2; q++) {
                int j = 2 * p + q;
                mma_bf16(c[j], ah, bh + 2 * q);
                mma_bf16(c[j], ah, bl + 2 * q);
                mma_bf16(c[j], al, bh + 2 * q);
            }
        }
    }
    __syncthreads();

    // stage D [64][128] in smem (stride 132), then coalesced split stores
    float* ds = (float*)smem;
#pragma unroll
    for (int j = 0; j < 8; j++) {
        int r = mw * 16 + g;
        int col = nw * 64 + j * 8 + 2 * t;
        ds[r * 132 + col] = c[j][0];
        ds[r * 132 + col + 1] = c[j][1];
        ds[(r + 8) * 132 + col] = c[j][2];
        ds[(r + 8) * 132 + col + 1] = c[j][3];
    }
    __syncthreads();
    for (int i = tid; i < 64 * 32; i += 256) {
        int mm = i >> 5, cq = (i & 31) * 4;
        int gr = row0 + mm;
        if (gr < Nrows) {
            float4 v = *(float4*)(&ds[mm * 132 + cq]);
            if (cq < 64) *(float4*)(outa + (size_t)gr * 64 + cq) = v;
            else *(float4*)(outr + (size_t)gr * 64 + (cq - 64)) = v;
        }
    }
}

// ---------------- CSR build (fused across both relations) ----------------
__global__ void zero_counts_kernel() {
    int i = blockIdx.x * blockDim.x + threadIdx.x;
    if (i < NG) g_cur_g[i] = 0;
    if (i < ND) g_cur_d[i] = 0;
}
__global__ void hist_both(const int* __restrict__ dst_dg, const int* __restrict__ dst_gd, int e) {
    int i = blockIdx.x * blockDim.x + threadIdx.x;
    if (i < e) atomicAdd(&g_cur_g[dst_dg[i]], 1);
    else if (i < 2 * e) atomicAdd(&g_cur_d[dst_gd[i - e]], 1);
}
__global__ void sbs_both(int nb_g) {
    __shared__ int sdata[256];
    int tid = threadIdx.x;
    const int* cnt;
    int n, bi;
    int* bsum;
    if (blockIdx.x < (unsigned)nb_g) { cnt = g_cur_g; n = NG; bi = blockIdx.x; bsum = g_bs_g; }
    else { cnt = g_cur_d; n = ND; bi = blockIdx.x - nb_g; bsum = g_bs_d; }
    int base = bi * 2048;
    int s = 0;
    for (int i = tid; i < 2048; i += 256) {
        int idx = base + i;
        if (idx < n) s += cnt[idx];
    }
    sdata[tid] = s;
    __syncthreads();
    for (int o = 128; o > 0; o >>= 1) {
        if (tid < o) sdata[tid] += sdata[tid + o];
        __syncthreads();
    }
    if (tid == 0) bsum[bi] = sdata[0];
}
__global__ void small_both(int nb_g, int nb_d) {
    __shared__ int s[64];
    int tid = threadIdx.x;
    int* bs = (blockIdx.x == 0) ? g_bs_g : g_bs_d;
    int nb = (blockIdx.x == 0) ? nb_g : nb_d;
    int orig = (tid < nb) ? bs[tid] : 0;
    s[tid] = orig;
    __syncthreads();
    for (int o = 1; o < 64; o <<= 1) {
        int v = (tid >= o) ? s[tid - o] : 0;
        __syncthreads();
        s[tid] += v;
        __syncthreads();
    }
    if (tid < nb) bs[tid] = s[tid] - orig;
}
__global__ void fin_both(int nb_g) {
    __shared__ int sh[256];
    int tid = threadIdx.x;
    int *cnt, *row_ptr, *cursor;
    const int* bsums;
    int n, bi;
    if (blockIdx.x < (unsigned)nb_g) {
        cnt = g_cur_g; row_ptr = g_rp_g; cursor = g_cur_g; bsums = g_bs_g; n = NG; bi = blockIdx.x;
    } else {
        cnt = g_cur_d; row_ptr = g_rp_d; cursor = g_cur_d; bsums = g_bs_d; n = ND; bi = blockIdx.x - nb_g;
    }
    int base = bi * 2048 + tid * 8;
    int v[8];
    int tsum = 0;
#pragma unroll
    for (int i = 0; i < 8; i++) {
        int idx = base + i;
        v[i] = (idx < n) ? cnt[idx] : 0;
        tsum += v[i];
    }
    sh[tid] = tsum;
    __syncthreads();
    for (int o = 1; o < 256; o <<= 1) {
        int add = (tid >= o) ? sh[tid - o] : 0;
        __syncthreads();
        sh[tid] += add;
        __syncthreads();
    }
    int run = sh[tid] - tsum + bsums[bi];
#pragma unroll
    for (int i = 0; i < 8; i++) {
        int idx = base + i;
        if (idx < n) {
            cursor[idx] = run;
            run += v[i];
            row_ptr[idx + 1] = run;
        }
    }
    if (bi == 0 && tid == 0) row_ptr[0] = 0;
}
__global__ void scatter_both(const int* __restrict__ src_dg, const int* __restrict__ dst_dg,
                             const int* __restrict__ src_gd, const int* __restrict__ dst_gd,
                             int e) {
    int i = blockIdx.x * blockDim.x + threadIdx.x;
    if (i < e) {
        int p = atomicAdd(&g_cur_g[dst_dg[i]], 1);
        g_col_dg[p] = src_dg[i];
    } else if (i < 2 * e) {
        int j = i - e;
        int p = atomicAdd(&g_cur_d[dst_gd[j]], 1);
        g_col_gd[p] = src_gd[j];
    }
}

// ---------------- fused mean-aggregate (both relations), float2, MLP-2 ----------------
// out[n][:] = mean_e a_src[col[e]][:] + bias + r_self[n][:]
__global__ void aggregate_both(
    const float* __restrict__ asrc_g, const float* __restrict__ rself_g,
    const float* __restrict__ bias_g, float* __restrict__ out_g,
    const float* __restrict__ asrc_d, const float* __restrict__ rself_d,
    const float* __restrict__ bias_d, float* __restrict__ out_d,
    int gblocks) {
    const float *asrc, *rself, *bias;
    float* out;
    const int *rp, *col;
    int ndst, t;
    if (blockIdx.x < (unsigned)gblocks) {
        asrc = asrc_g; rself = rself_g; bias = bias_g; out = out_g;
        rp = g_rp_g; col = g_col_dg; ndst = NG;
        t = blockIdx.x * 256 + threadIdx.x;
    } else {
        asrc = asrc_d; rself = rself_d; bias = bias_d; out = out_d;
        rp = g_rp_d; col = g_col_gd; ndst = ND;
        t = (blockIdx.x - gblocks) * 256 + threadIdx.x;
    }
    int n = t >> 5;
    int d2 = (t & 31) * 2;
    if (n >= ndst) return;
    int beg = rp[n], end = rp[n + 1];
    float ax = 0.f, ay = 0.f;
    int e = beg;
    for (; e + 2 <= end; e += 2) {
        int c0 = __ldg(&col[e]);
        int c1 = __ldg(&col[e + 1]);
        float2 v0 = *(const float2*)(asrc + (size_t)c0 * 64 + d2);
        float2 v1 = *(const float2*)(asrc + (size_t)c1 * 64 + d2);
        ax += v0.x + v1.x;
        ay += v0.y + v1.y;
    }
    if (e < end) {
        int c0 = __ldg(&col[e]);
        float2 v0 = *(const float2*)(asrc + (size_t)c0 * 64 + d2);
        ax += v0.x;
        ay += v0.y;
    }
    int deg = end - beg;
    float inv = (deg > 0) ? 1.f / (float)deg : 0.f;
    float2 rs = *(const float2*)(rself + (size_t)n * 64 + d2);
    float2 o;
    o.x = ax * inv + bias[d2] + rs.x;
    o.y = ay * inv + bias[d2 + 1] + rs.y;
    *(float2*)(out + (size_t)n * 64 + d2) = o;
}

// ---------------- host launcher ----------------
extern "C" void kernel_launch(void* const* d_in, const int* in_sizes, int n_in,
                              void* d_out, int out_size) {
    const float* x_d = (const float*)d_in[0];
    const float* x_g = (const float*)d_in[1];
    const int* src_dg = (const int*)d_in[2];
    const int* dst_dg = (const int*)d_in[3];
    const int* src_gd = (const int*)d_in[4];
    const int* dst_gd = (const int*)d_in[5];
    const float* Wl1_dg = (const float*)d_in[6];
    const float* bl1_dg = (const float*)d_in[7];
    const float* Wr1_dg = (const float*)d_in[8];
    const float* Wl1_gd = (const float*)d_in[9];
    const float* bl1_gd = (const float*)d_in[10];
    const float* Wr1_gd = (const float*)d_in[11];
    const float* Wl2_dg = (const float*)d_in[12];
    const float* bl2_dg = (const float*)d_in[13];
    const float* Wr2_dg = (const float*)d_in[14];
    const float* Wl2_gd = (const float*)d_in[15];
    const float* bl2_gd = (const float*)d_in[16];
    const float* Wr2_gd = (const float*)d_in[17];
    float* out = (float*)d_out;

    int E = in_sizes[2];
    if (E > NE) E = NE;

    float *ad, *rd, *ag, *rg, *d1, *g1;
    cudaGetSymbolAddress((void**)&ad, g_a_d);
    cudaGetSymbolAddress((void**)&rd, g_r_d);
    cudaGetSymbolAddress((void**)&ag, g_a_g);
    cudaGetSymbolAddress((void**)&rg, g_r_g);
    cudaGetSymbolAddress((void**)&d1, g_d1);
    cudaGetSymbolAddress((void**)&g1, g_g1);

    const int tilesD = (ND + 63) / 64;   // 782
    const int tilesG = (NG + 63) / 64;   // 1563
    const int dsz128 = (2 * 64 + 2 * 128) * (128 + 8) * 2;  // 104448
    const int dsz64 = (2 * 64 + 2 * 128) * (64 + 8) * 2;    // 55296
    cudaFuncSetAttribute(gemm_mma<128>, cudaFuncAttributeMaxDynamicSharedMemorySize, dsz128);
    cudaFuncSetAttribute(gemm_mma<64>, cudaFuncAttributeMaxDynamicSharedMemorySize, dsz64);

    const int nb_g = (NG + 2047) / 2048;  // 49
    const int nb_d = (ND + 2047) / 2048;  // 25
    const int gblocks = (NG * 32 + 255) / 256;  // 12500
    const int dblocks = (ND * 32 + 255) / 256;  // 6250

    // 1..4: gemm1 sits 4th (ncu appears to capture ~the 4th launch)
    prep_w_kernel<<<4, 256>>>(Wl1_dg, Wr1_gd, Wl1_gd, Wr1_dg,
                              Wl2_dg, Wr2_gd, Wl2_gd, Wr2_dg);                  // 1
    zero_counts_kernel<<<(NG + 255) / 256, 256>>>();                            // 2
    hist_both<<<(2 * E + 255) / 256, 256>>>(dst_dg, dst_gd, E);                 // 3
    gemm_mma<128><<<tilesD + tilesG, 256, dsz128>>>(x_d, x_g, ad, rd, ag, rg,
                                                    0, 1, ND, NG, tilesD);      // 4
    sbs_both<<<nb_g + nb_d, 256>>>(nb_g);                                       // 5
    small_both<<<2, 64>>>(nb_g, nb_d);                                          // 6
    fin_both<<<nb_g + nb_d, 256>>>(nb_g);                                       // 7
    scatter_both<<<(2 * E + 255) / 256, 256>>>(src_dg, dst_dg, src_gd, dst_gd, E); // 8

    // layer-1 aggregate: g1 = mean_dg(a_d) + bl1_dg + r_g ; d1 = mean_gd(a_g) + bl1_gd + r_d
    aggregate_both<<<gblocks + dblocks, 256>>>(ad, rg, bl1_dg, g1,
                                               ag, rd, bl1_gd, d1, gblocks);    // 9

    // layer-2 transform
    gemm_mma<64><<<tilesD + tilesG, 256, dsz64>>>(d1, g1, ad, rd, ag, rg,
                                                  2, 3, ND, NG, tilesD);        // 10

    // layer-2 aggregate: g2 -> out[ND*64..], d2 -> out[0..]
    aggregate_both<<<gblocks + dblocks, 256>>>(ad, rg, bl2_dg, out + (size_t)ND * 64,
                                               ag, rd, bl2_gd, out, gblocks);   // 11
}

// round 5
// speedup vs baseline: 1.8085x; 1.1971x over previous
#include <cuda_runtime.h>
#include <cuda_bf16.h>
#include <cstdint>

#define ND 50000
#define NG 100000
#define NE 600000

// ---------------- static scratch ----------------
__device__ __align__(16) float g_a_d[(size_t)ND * 64];
__device__ __align__(16) float g_r_d[(size_t)ND * 64];
__device__ __align__(16) float g_a_g[(size_t)NG * 64];
__device__ __align__(16) float g_r_g[(size_t)NG * 64];
__device__ __align__(16) float g_d1[(size_t)ND * 64];
__device__ __align__(16) float g_g1[(size_t)NG * 64];
// 4 weight images: [n=128][k=K] bf16, padded rows (K+8), hi then lo. slot = 69632 B
__device__ __align__(16) char g_wimg[4 * 69632];

__device__ int g_rp_g[NG + 1];
__device__ int g_rp_d[ND + 1];
__device__ int g_cur_g[NG];
__device__ int g_cur_d[ND];
__device__ int g_col_dg[NE];
__device__ int g_col_gd[NE];
__device__ int g_bs_g[64];
__device__ int g_bs_d[64];

// ---------------- helpers ----------------
__device__ __forceinline__ uint32_t smem_u32(const void* p) {
    uint32_t a;
    asm("{ .reg .u64 t; cvta.to.shared.u64 t, %1; cvt.u32.u64 %0, t; }" : "=r"(a) : "l"(p));
    return a;
}
__device__ __forceinline__ void ldm4(uint32_t* r, uint32_t addr) {
    asm volatile("ldmatrix.sync.aligned.m8n8.x4.shared.b16 {%0,%1,%2,%3}, [%4];"
                 : "=r"(r[0]), "=r"(r[1]), "=r"(r[2]), "=r"(r[3]) : "r"(addr));
}
__device__ __forceinline__ void mma_bf16(float* c, const uint32_t* a, const uint32_t* b) {
    asm volatile(
        "mma.sync.aligned.m16n8k16.row.col.f32.bf16.bf16.f32 "
        "{%0,%1,%2,%3}, {%4,%5,%6,%7}, {%8,%9}, {%0,%1,%2,%3};"
        : "+f"(c[0]), "+f"(c[1]), "+f"(c[2]), "+f"(c[3])
        : "r"(a[0]), "r"(a[1]), "r"(a[2]), "r"(a[3]), "r"(b[0]), "r"(b[1]));
}
// split two fp32 into packed bf16x2 hi (returned) and lo (out param)
__device__ __forceinline__ uint32_t bsplit(float x, float y, uint32_t& lo) {
    __nv_bfloat16 hx = __float2bfloat16(x), hy = __float2bfloat16(y);
    __nv_bfloat16 lx = __float2bfloat16(x - __bfloat162float(hx));
    __nv_bfloat16 ly = __float2bfloat16(y - __bfloat162float(hy));
    lo = (uint32_t)__bfloat16_as_ushort(lx) | ((uint32_t)__bfloat16_as_ushort(ly) << 16);
    return (uint32_t)__bfloat16_as_ushort(hx) | ((uint32_t)__bfloat16_as_ushort(hy) << 16);
}

// ---------------- weight image prep ----------------
__global__ void prep_w_kernel(const float* __restrict__ Wa0, const float* __restrict__ Wb0,
                              const float* __restrict__ Wa1, const float* __restrict__ Wb1,
                              const float* __restrict__ Wa2, const float* __restrict__ Wb2,
                              const float* __restrict__ Wa3, const float* __restrict__ Wb3) {
    int img = blockIdx.x;
    const float *Wa, *Wb;
    int K;
    if (img == 0) { Wa = Wa0; Wb = Wb0; K = 128; }
    else if (img == 1) { Wa = Wa1; Wb = Wb1; K = 128; }
    else if (img == 2) { Wa = Wa2; Wb = Wb2; K = 64; }
    else { Wa = Wa3; Wb = Wb3; K = 64; }
    int rowb = (K + 8) * 2;
    char* hi_img = g_wimg + (size_t)img * 69632;
    char* lo_img = hi_img + 128 * rowb;
    for (int i = threadIdx.x; i < 128 * K; i += blockDim.x) {
        int n = i / K, k = i % K;
        float w = (n < 64) ? Wa[k * 64 + n] : Wb[k * 64 + (n - 64)];
        __nv_bfloat16 h = __float2bfloat16(w);
        __nv_bfloat16 l = __float2bfloat16(w - __bfloat162float(h));
        *(__nv_bfloat16*)(hi_img + n * rowb + k * 2) = h;
        *(__nv_bfloat16*)(lo_img + n * rowb + k * 2) = l;
    }
}

// ---------------- persistent HMMA GEMM: [a|r](N,64+64) = X[N,K] @ W -------------
// 8 warps = 4m x 2n. B (hi/lo) resident in smem; A streamed from global fp32,
// bf16 hi/lo split in registers. Direct register->global epilogue.
template <int K>
__global__ __launch_bounds__(256, 3) void gemm_mma(
    const float* __restrict__ Xd, const float* __restrict__ Xg,
    float* __restrict__ ad, float* __restrict__ rd,
    float* __restrict__ ag, float* __restrict__ rg,
    int img_d, int img_g, int Ndis, int Ngen,
    int tilesD, int tilesG, int Pd) {
    constexpr int STR = K + 8;
    constexpr int ROWB = STR * 2;
    constexpr int BMAT = 128 * ROWB;
    constexpr int NSTEP = K / 16;
    extern __shared__ __align__(16) char smem[];   // B hi then lo

    const float* X;
    float *outa, *outr;
    int Nrows, img, tbeg, tnum, tstep;
    if ((int)blockIdx.x < Pd) {
        X = Xd; outa = ad; outr = rd; Nrows = Ndis; img = img_d;
        tbeg = blockIdx.x; tnum = tilesD; tstep = Pd;
    } else {
        X = Xg; outa = ag; outr = rg; Nrows = Ngen; img = img_g;
        tbeg = blockIdx.x - Pd; tnum = tilesG; tstep = gridDim.x - Pd;
    }

    // load B hi/lo once
    {
        const char* im = g_wimg + (size_t)img * 69632;
        for (int v = threadIdx.x; v < (2 * BMAT) / 16; v += 256)
            ((float4*)smem)[v] = ((const float4*)im)[v];
    }
    __syncthreads();

    const int w = threadIdx.x >> 5, lane = threadIdx.x & 31;
    const int mw = w >> 1, nw = w & 1;
    const int g = lane >> 2, t = lane & 3;
    const uint32_t bB = smem_u32(smem) +
                        (uint32_t)((nw * 64 + ((lane >> 4) << 3) + (lane & 7)) * ROWB +
                                   ((lane >> 3) & 1) * 16);
    float* const o = (nw == 0) ? outa : outr;

    for (int tb = tbeg; tb < tnum; tb += tstep) {
        const int r0 = tb * 64 + mw * 16 + g;
        const int r1 = r0 + 8;
        const bool v0 = r0 < Nrows, v1 = r1 < Nrows;
        const float* x0 = X + (size_t)r0 * K + 2 * t;
        const float* x1 = X + (size_t)r1 * K + 2 * t;

        float c[8][4];
#pragma unroll
        for (int j = 0; j < 8; j++)
#pragma unroll
            for (int q = 0; q < 4; q++) c[j][q] = 0.f;

#pragma unroll
        for (int s = 0; s < NSTEP; s++) {
            const int ke = s * 16;
            float2 z = make_float2(0.f, 0.f);
            float2 p00 = v0 ? *(const float2*)(x0 + ke) : z;
            float2 p01 = v0 ? *(const float2*)(x0 + ke + 8) : z;
            float2 p10 = v1 ? *(const float2*)(x1 + ke) : z;
            float2 p11 = v1 ? *(const float2*)(x1 + ke + 8) : z;
            uint32_t ah[4], al[4];
            ah[0] = bsplit(p00.x, p00.y, al[0]);
            ah[1] = bsplit(p10.x, p10.y, al[1]);
            ah[2] = bsplit(p01.x, p01.y, al[2]);
            ah[3] = bsplit(p11.x, p11.y, al[3]);
            const uint32_t ko = (uint32_t)(s * 32);
#pragma unroll
            for (int p = 0; p < 4; p++) {
                uint32_t bh[4], bl[4];
                ldm4(bh, bB + p * 16 * ROWB + ko);
                ldm4(bl, bB + BMAT + p * 16 * ROWB + ko);
#pragma unroll
                for (int q = 0; q < 2; q++) {
                    int j = 2 * p + q;
                    mma_bf16(c[j], ah, bh + 2 * q);
                    mma_bf16(c[j], ah, bl + 2 * q);
                    mma_bf16(c[j], al, bh + 2 * q);
                }
            }
        }

        // direct epilogue: nw=0 warps own cols 0..63 (a), nw=1 own 64..127 (r)
#pragma unroll
        for (int j = 0; j < 8; j++) {
            int col = j * 8 + 2 * t;
            if (v0) *(float2*)(o + (size_t)r0 * 64 + col) = make_float2(c[j][0], c[j][1]);
            if (v1) *(float2*)(o + (size_t)r1 * 64 + col) = make_float2(c[j][2], c[j][3]);
        }
    }
}

// ---------------- CSR build (fused across both relations) ----------------
__global__ void zero_counts_kernel() {
    int i = blockIdx.x * blockDim.x + threadIdx.x;
    if (i < NG) g_cur_g[i] = 0;
    if (i < ND) g_cur_d[i] = 0;
}
__global__ void hist_both(const int* __restrict__ dst_dg, const int* __restrict__ dst_gd, int e) {
    int i = blockIdx.x * blockDim.x + threadIdx.x;
    if (i < e) atomicAdd(&g_cur_g[dst_dg[i]], 1);
    else if (i < 2 * e) atomicAdd(&g_cur_d[dst_gd[i - e]], 1);
}
__global__ void sbs_both(int nb_g) {
    __shared__ int sdata[256];
    int tid = threadIdx.x;
    const int* cnt;
    int n, bi;
    int* bsum;
    if (blockIdx.x < (unsigned)nb_g) { cnt = g_cur_g; n = NG; bi = blockIdx.x; bsum = g_bs_g; }
    else { cnt = g_cur_d; n = ND; bi = blockIdx.x - nb_g; bsum = g_bs_d; }
    int base = bi * 2048;
    int s = 0;
    for (int i = tid; i < 2048; i += 256) {
        int idx = base + i;
        if (idx < n) s += cnt[idx];
    }
    sdata[tid] = s;
    __syncthreads();
    for (int o = 128; o > 0; o >>= 1) {
        if (tid < o) sdata[tid] += sdata[tid + o];
        __syncthreads();
    }
    if (tid == 0) bsum[bi] = sdata[0];
}
__global__ void small_both(int nb_g, int nb_d) {
    __shared__ int s[64];
    int tid = threadIdx.x;
    int* bs = (blockIdx.x == 0) ? g_bs_g : g_bs_d;
    int nb = (blockIdx.x == 0) ? nb_g : nb_d;
    int orig = (tid < nb) ? bs[tid] : 0;
    s[tid] = orig;
    __syncthreads();
    for (int o = 1; o < 64; o <<= 1) {
        int v = (tid >= o) ? s[tid - o] : 0;
        __syncthreads();
        s[tid] += v;
        __syncthreads();
    }
    if (tid < nb) bs[tid] = s[tid] - orig;
}
__global__ void fin_both(int nb_g) {
    __shared__ int sh[256];
    int tid = threadIdx.x;
    int *cnt, *row_ptr, *cursor;
    const int* bsums;
    int n, bi;
    if (blockIdx.x < (unsigned)nb_g) {
        cnt = g_cur_g; row_ptr = g_rp_g; cursor = g_cur_g; bsums = g_bs_g; n = NG; bi = blockIdx.x;
    } else {
        cnt = g_cur_d; row_ptr = g_rp_d; cursor = g_cur_d; bsums = g_bs_d; n = ND; bi = blockIdx.x - nb_g;
    }
    int base = bi * 2048 + tid * 8;
    int v[8];
    int tsum = 0;
#pragma unroll
    for (int i = 0; i < 8; i++) {
        int idx = base + i;
        v[i] = (idx < n) ? cnt[idx] : 0;
        tsum += v[i];
    }
    sh[tid] = tsum;
    __syncthreads();
    for (int o = 1; o < 256; o <<= 1) {
        int add = (tid >= o) ? sh[tid - o] : 0;
        __syncthreads();
        sh[tid] += add;
        __syncthreads();
    }
    int run = sh[tid] - tsum + bsums[bi];
#pragma unroll
    for (int i = 0; i < 8; i++) {
        int idx = base + i;
        if (idx < n) {
            cursor[idx] = run;
            run += v[i];
            row_ptr[idx + 1] = run;
        }
    }
    if (bi == 0 && tid == 0) row_ptr[0] = 0;
}
__global__ void scatter_both(const int* __restrict__ src_dg, const int* __restrict__ dst_dg,
                             const int* __restrict__ src_gd, const int* __restrict__ dst_gd,
                             int e) {
    int i = blockIdx.x * blockDim.x + threadIdx.x;
    if (i < e) {
        int p = atomicAdd(&g_cur_g[dst_dg[i]], 1);
        g_col_dg[p] = src_dg[i];
    } else if (i < 2 * e) {
        int j = i - e;
        int p = atomicAdd(&g_cur_d[dst_gd[j]], 1);
        g_col_gd[p] = src_gd[j];
    }
}

// ---------------- fused mean-aggregate (both relations), float2, MLP-2 ----------------
__global__ void aggregate_both(
    const float* __restrict__ asrc_g, const float* __restrict__ rself_g,
    const float* __restrict__ bias_g, float* __restrict__ out_g,
    const float* __restrict__ asrc_d, const float* __restrict__ rself_d,
    const float* __restrict__ bias_d, float* __restrict__ out_d,
    int gblocks) {
    const float *asrc, *rself, *bias;
    float* out;
    const int *rp, *col;
    int ndst, t;
    if (blockIdx.x < (unsigned)gblocks) {
        asrc = asrc_g; rself = rself_g; bias = bias_g; out = out_g;
        rp = g_rp_g; col = g_col_dg; ndst = NG;
        t = blockIdx.x * 256 + threadIdx.x;
    } else {
        asrc = asrc_d; rself = rself_d; bias = bias_d; out = out_d;
        rp = g_rp_d; col = g_col_gd; ndst = ND;
        t = (blockIdx.x - gblocks) * 256 + threadIdx.x;
    }
    int n = t >> 5;
    int d2 = (t & 31) * 2;
    if (n >= ndst) return;
    int beg = rp[n], end = rp[n + 1];
    float ax = 0.f, ay = 0.f;
    int e = beg;
    for (; e + 2 <= end; e += 2) {
        int c0 = __ldg(&col[e]);
        int c1 = __ldg(&col[e + 1]);
        float2 v0 = *(const float2*)(asrc + (size_t)c0 * 64 + d2);
        float2 v1 = *(const float2*)(asrc + (size_t)c1 * 64 + d2);
        ax += v0.x + v1.x;
        ay += v0.y + v1.y;
    }
    if (e < end) {
        int c0 = __ldg(&col[e]);
        float2 v0 = *(const float2*)(asrc + (size_t)c0 * 64 + d2);
        ax += v0.x;
        ay += v0.y;
    }
    int deg = end - beg;
    float inv = (deg > 0) ? 1.f / (float)deg : 0.f;
    float2 rs = *(const float2*)(rself + (size_t)n * 64 + d2);
    float2 o;
    o.x = ax * inv + bias[d2] + rs.x;
    o.y = ay * inv + bias[d2 + 1] + rs.y;
    *(float2*)(out + (size_t)n * 64 + d2) = o;
}

// ---------------- host launcher ----------------
extern "C" void kernel_launch(void* const* d_in, const int* in_sizes, int n_in,
                              void* d_out, int out_size) {
    const float* x_d = (const float*)d_in[0];
    const float* x_g = (const float*)d_in[1];
    const int* src_dg = (const int*)d_in[2];
    const int* dst_dg = (const int*)d_in[3];
    const int* src_gd = (const int*)d_in[4];
    const int* dst_gd = (const int*)d_in[5];
    const float* Wl1_dg = (const float*)d_in[6];
    const float* bl1_dg = (const float*)d_in[7];
    const float* Wr1_dg = (const float*)d_in[8];
    const float* Wl1_gd = (const float*)d_in[9];
    const float* bl1_gd = (const float*)d_in[10];
    const float* Wr1_gd = (const float*)d_in[11];
    const float* Wl2_dg = (const float*)d_in[12];
    const float* bl2_dg = (const float*)d_in[13];
    const float* Wr2_dg = (const float*)d_in[14];
    const float* Wl2_gd = (const float*)d_in[15];
    const float* bl2_gd = (const float*)d_in[16];
    const float* Wr2_gd = (const float*)d_in[17];
    float* out = (float*)d_out;

    int E = in_sizes[2];
    if (E > NE) E = NE;

    float *ad, *rd, *ag, *rg, *d1, *g1;
    cudaGetSymbolAddress((void**)&ad, g_a_d);
    cudaGetSymbolAddress((void**)&rd, g_r_d);
    cudaGetSymbolAddress((void**)&ag, g_a_g);
    cudaGetSymbolAddress((void**)&rg, g_r_g);
    cudaGetSymbolAddress((void**)&d1, g_d1);
    cudaGetSymbolAddress((void**)&g1, g_g1);

    const int tilesD = (ND + 63) / 64;   // 782
    const int tilesG = (NG + 63) / 64;   // 1563
    const int Pd = 148, Pg = 296;        // persistent CTA split (1:2 ~ tile ratio)
    const int smem128 = 2 * 128 * (128 + 8) * 2;  // 69632 (B hi/lo)
    const int smem64 = 2 * 128 * (64 + 8) * 2;    // 36864
    cudaFuncSetAttribute(gemm_mma<128>, cudaFuncAttributeMaxDynamicSharedMemorySize, smem128);
    cudaFuncSetAttribute(gemm_mma<64>, cudaFuncAttributeMaxDynamicSharedMemorySize, smem64);

    const int nb_g = (NG + 2047) / 2048;  // 49
    const int nb_d = (ND + 2047) / 2048;  // 25
    const int gblocks = (NG * 32 + 255) / 256;  // 12500
    const int dblocks = (ND * 32 + 255) / 256;  // 6250

    prep_w_kernel<<<4, 256>>>(Wl1_dg, Wr1_gd, Wl1_gd, Wr1_dg,
                              Wl2_dg, Wr2_gd, Wl2_gd, Wr2_dg);                  // 1
    zero_counts_kernel<<<(NG + 255) / 256, 256>>>();                            // 2
    hist_both<<<(2 * E + 255) / 256, 256>>>(dst_dg, dst_gd, E);                 // 3
    gemm_mma<128><<<Pd + Pg, 256, smem128>>>(x_d, x_g, ad, rd, ag, rg,
                                             0, 1, ND, NG, tilesD, tilesG, Pd); // 4 (profiled)
    sbs_both<<<nb_g + nb_d, 256>>>(nb_g);                                       // 5
    small_both<<<2, 64>>>(nb_g, nb_d);                                          // 6
    fin_both<<<nb_g + nb_d, 256>>>(nb_g);                                       // 7
    scatter_both<<<(2 * E + 255) / 256, 256>>>(src_dg, dst_dg, src_gd, dst_gd, E); // 8

    aggregate_both<<<gblocks + dblocks, 256>>>(ad, rg, bl1_dg, g1,
                                               ag, rd, bl1_gd, d1, gblocks);    // 9

    gemm_mma<64><<<Pd + Pg, 256, smem64>>>(d1, g1, ad, rd, ag, rg,
                                           2, 3, ND, NG, tilesD, tilesG, Pd);   // 10

    aggregate_both<<<gblocks + dblocks, 256>>>(ad, rg, bl2_dg, out + (size_t)ND * 64,
                                               ag, rd, bl2_gd, out, gblocks);   // 11
}

// round 6
// speedup vs baseline: 1.9666x; 1.0874x over previous
#include <cuda_runtime.h>
#include <cuda_bf16.h>
#include <cstdint>

#define ND 50000
#define NG 100000
#define NE 600000

// ---------------- static scratch ----------------
__device__ __align__(16) float g_a_d[(size_t)ND * 64];
__device__ __align__(16) float g_r_d[(size_t)ND * 64];
__device__ __align__(16) float g_a_g[(size_t)NG * 64];
__device__ __align__(16) float g_r_g[(size_t)NG * 64];
__device__ __align__(16) float g_d1[(size_t)ND * 64];
__device__ __align__(16) float g_g1[(size_t)NG * 64];
// 4 weight images: [n=128][k=K] bf16, padded rows (K+8), hi then lo. slot = 69632 B
__device__ __align__(16) char g_wimg[4 * 69632];

__device__ int g_rp_g[NG + 1];
__device__ int g_rp_d[ND + 1];
__device__ int g_cur_g[NG];
__device__ int g_cur_d[ND];
__device__ int g_col_dg[NE];
__device__ int g_col_gd[NE];
__device__ int g_bs_g[64];
__device__ int g_bs_d[64];

// ---------------- helpers ----------------
__device__ __forceinline__ uint32_t smem_u32(const void* p) {
    uint32_t a;
    asm("{ .reg .u64 t; cvta.to.shared.u64 t, %1; cvt.u32.u64 %0, t; }" : "=r"(a) : "l"(p));
    return a;
}
__device__ __forceinline__ void ldm4(uint32_t* r, uint32_t addr) {
    asm volatile("ldmatrix.sync.aligned.m8n8.x4.shared.b16 {%0,%1,%2,%3}, [%4];"
                 : "=r"(r[0]), "=r"(r[1]), "=r"(r[2]), "=r"(r[3]) : "r"(addr));
}
__device__ __forceinline__ void mma_bf16(float* c, const uint32_t* a, const uint32_t* b) {
    asm volatile(
        "mma.sync.aligned.m16n8k16.row.col.f32.bf16.bf16.f32 "
        "{%0,%1,%2,%3}, {%4,%5,%6,%7}, {%8,%9}, {%0,%1,%2,%3};"
        : "+f"(c[0]), "+f"(c[1]), "+f"(c[2]), "+f"(c[3])
        : "r"(a[0]), "r"(a[1]), "r"(a[2]), "r"(a[3]), "r"(b[0]), "r"(b[1]));
}
__device__ __forceinline__ uint32_t bsplit(float x, float y, uint32_t& lo) {
    __nv_bfloat16 hx = __float2bfloat16(x), hy = __float2bfloat16(y);
    __nv_bfloat16 lx = __float2bfloat16(x - __bfloat162float(hx));
    __nv_bfloat16 ly = __float2bfloat16(y - __bfloat162float(hy));
    lo = (uint32_t)__bfloat16_as_ushort(lx) | ((uint32_t)__bfloat16_as_ushort(ly) << 16);
    return (uint32_t)__bfloat16_as_ushort(hx) | ((uint32_t)__bfloat16_as_ushort(hy) << 16);
}

// ---------------- weight image prep ----------------
__global__ void prep_w_kernel(const float* __restrict__ Wa0, const float* __restrict__ Wb0,
                              const float* __restrict__ Wa1, const float* __restrict__ Wb1,
                              const float* __restrict__ Wa2, const float* __restrict__ Wb2,
                              const float* __restrict__ Wa3, const float* __restrict__ Wb3) {
    int img = blockIdx.x;
    const float *Wa, *Wb;
    int K;
    if (img == 0) { Wa = Wa0; Wb = Wb0; K = 128; }
    else if (img == 1) { Wa = Wa1; Wb = Wb1; K = 128; }
    else if (img == 2) { Wa = Wa2; Wb = Wb2; K = 64; }
    else { Wa = Wa3; Wb = Wb3; K = 64; }
    int rowb = (K + 8) * 2;
    char* hi_img = g_wimg + (size_t)img * 69632;
    char* lo_img = hi_img + 128 * rowb;
    for (int i = threadIdx.x; i < 128 * K; i += blockDim.x) {
        int n = i / K, k = i % K;
        float w = (n < 64) ? Wa[k * 64 + n] : Wb[k * 64 + (n - 64)];
        __nv_bfloat16 h = __float2bfloat16(w);
        __nv_bfloat16 l = __float2bfloat16(w - __bfloat162float(h));
        *(__nv_bfloat16*)(hi_img + n * rowb + k * 2) = h;
        *(__nv_bfloat16*)(lo_img + n * rowb + k * 2) = l;
    }
}

// ---------------- persistent HMMA GEMM: [a|r](N,64+64) = X[N,K] @ W -------------
// 8 warps = 4m x 2n, CTA tile M=128 (each warp: 2 m16 sub-tiles => B frags feed 2x MMAs).
// B (hi/lo) resident in smem; A streamed from global fp32, bf16 hi/lo split in regs.
template <int K>
__global__ __launch_bounds__(256, 2) void gemm_mma(
    const float* __restrict__ Xd, const float* __restrict__ Xg,
    float* __restrict__ ad, float* __restrict__ rd,
    float* __restrict__ ag, float* __restrict__ rg,
    int img_d, int img_g, int Ndis, int Ngen,
    int tilesD, int tilesG, int Pd) {
    constexpr int STR = K + 8;
    constexpr int ROWB = STR * 2;
    constexpr int BMAT = 128 * ROWB;
    constexpr int NSTEP = K / 16;
    extern __shared__ __align__(16) char smem[];   // B hi then lo

    const float* X;
    float *outa, *outr;
    int Nrows, img, tbeg, tnum, tstep;
    if ((int)blockIdx.x < Pd) {
        X = Xd; outa = ad; outr = rd; Nrows = Ndis; img = img_d;
        tbeg = blockIdx.x; tnum = tilesD; tstep = Pd;
    } else {
        X = Xg; outa = ag; outr = rg; Nrows = Ngen; img = img_g;
        tbeg = blockIdx.x - Pd; tnum = tilesG; tstep = gridDim.x - Pd;
    }

    // load B hi/lo once
    {
        const char* im = g_wimg + (size_t)img * 69632;
        for (int v = threadIdx.x; v < (2 * BMAT) / 16; v += 256)
            ((float4*)smem)[v] = ((const float4*)im)[v];
    }
    __syncthreads();

    const int w = threadIdx.x >> 5, lane = threadIdx.x & 31;
    const int mw = w >> 1, nw = w & 1;
    const int g = lane >> 2, t = lane & 3;
    const uint32_t bB = smem_u32(smem) +
                        (uint32_t)((nw * 64 + ((lane >> 4) << 3) + (lane & 7)) * ROWB +
                                   ((lane >> 3) & 1) * 16);
    float* const o = (nw == 0) ? outa : outr;

    for (int tb = tbeg; tb < tnum; tb += tstep) {
        const int rbase = tb * 128 + mw * 32 + g;
        const int r00 = rbase, r01 = rbase + 8;        // mt=0
        const int r10 = rbase + 16, r11 = rbase + 24;  // mt=1
        const bool v00 = r00 < Nrows, v01 = r01 < Nrows;
        const bool v10 = r10 < Nrows, v11 = r11 < Nrows;
        const float* x00 = X + (size_t)r00 * K + 2 * t;
        const float* x01 = X + (size_t)r01 * K + 2 * t;
        const float* x10 = X + (size_t)r10 * K + 2 * t;
        const float* x11 = X + (size_t)r11 * K + 2 * t;

        float c[2][8][4];
#pragma unroll
        for (int mt = 0; mt < 2; mt++)
#pragma unroll
            for (int j = 0; j < 8; j++)
#pragma unroll
                for (int q = 0; q < 4; q++) c[mt][j][q] = 0.f;

#pragma unroll
        for (int s = 0; s < NSTEP; s++) {
            const int ke = s * 16;
            const float2 z = make_float2(0.f, 0.f);
            float2 a00 = v00 ? *(const float2*)(x00 + ke) : z;
            float2 a00b = v00 ? *(const float2*)(x00 + ke + 8) : z;
            float2 a01 = v01 ? *(const float2*)(x01 + ke) : z;
            float2 a01b = v01 ? *(const float2*)(x01 + ke + 8) : z;
            float2 a10 = v10 ? *(const float2*)(x10 + ke) : z;
            float2 a10b = v10 ? *(const float2*)(x10 + ke + 8) : z;
            float2 a11 = v11 ? *(const float2*)(x11 + ke) : z;
            float2 a11b = v11 ? *(const float2*)(x11 + ke + 8) : z;
            uint32_t ah0[4], al0[4], ah1[4], al1[4];
            ah0[0] = bsplit(a00.x, a00.y, al0[0]);
            ah0[1] = bsplit(a01.x, a01.y, al0[1]);
            ah0[2] = bsplit(a00b.x, a00b.y, al0[2]);
            ah0[3] = bsplit(a01b.x, a01b.y, al0[3]);
            ah1[0] = bsplit(a10.x, a10.y, al1[0]);
            ah1[1] = bsplit(a11.x, a11.y, al1[1]);
            ah1[2] = bsplit(a10b.x, a10b.y, al1[2]);
            ah1[3] = bsplit(a11b.x, a11b.y, al1[3]);
            const uint32_t ko = (uint32_t)(s * 32);
#pragma unroll
            for (int p = 0; p < 4; p++) {
                uint32_t bh[4], bl[4];
                ldm4(bh, bB + p * 16 * ROWB + ko);
                ldm4(bl, bB + BMAT + p * 16 * ROWB + ko);
#pragma unroll
                for (int q = 0; q < 2; q++) {
                    int j = 2 * p + q;
                    mma_bf16(c[0][j], ah0, bh + 2 * q);
                    mma_bf16(c[0][j], ah0, bl + 2 * q);
                    mma_bf16(c[0][j], al0, bh + 2 * q);
                    mma_bf16(c[1][j], ah1, bh + 2 * q);
                    mma_bf16(c[1][j], ah1, bl + 2 * q);
                    mma_bf16(c[1][j], al1, bh + 2 * q);
                }
            }
        }

        // direct epilogue: nw=0 warps own cols 0..63 (a), nw=1 own 64..127 (r)
#pragma unroll
        for (int mt = 0; mt < 2; mt++) {
            const int ra = rbase + mt * 16;
            const int rb = ra + 8;
            const bool va = (mt == 0) ? v00 : v10;
            const bool vb = (mt == 0) ? v01 : v11;
#pragma unroll
            for (int j = 0; j < 8; j++) {
                int col = j * 8 + 2 * t;
                if (va) *(float2*)(o + (size_t)ra * 64 + col) = make_float2(c[mt][j][0], c[mt][j][1]);
                if (vb) *(float2*)(o + (size_t)rb * 64 + col) = make_float2(c[mt][j][2], c[mt][j][3]);
            }
        }
    }
}

// ---------------- CSR build (fused across both relations) ----------------
__global__ void zero_counts_kernel() {
    int i = blockIdx.x * blockDim.x + threadIdx.x;
    if (i < NG) g_cur_g[i] = 0;
    if (i < ND) g_cur_d[i] = 0;
}
__global__ void hist_both(const int* __restrict__ dst_dg, const int* __restrict__ dst_gd, int e) {
    int i = blockIdx.x * blockDim.x + threadIdx.x;
    if (i < e) atomicAdd(&g_cur_g[dst_dg[i]], 1);
    else if (i < 2 * e) atomicAdd(&g_cur_d[dst_gd[i - e]], 1);
}
__global__ void sbs_both(int nb_g) {
    __shared__ int sdata[256];
    int tid = threadIdx.x;
    const int* cnt;
    int n, bi;
    int* bsum;
    if (blockIdx.x < (unsigned)nb_g) { cnt = g_cur_g; n = NG; bi = blockIdx.x; bsum = g_bs_g; }
    else { cnt = g_cur_d; n = ND; bi = blockIdx.x - nb_g; bsum = g_bs_d; }
    int base = bi * 2048;
    int s = 0;
    for (int i = tid; i < 2048; i += 256) {
        int idx = base + i;
        if (idx < n) s += cnt[idx];
    }
    sdata[tid] = s;
    __syncthreads();
    for (int o = 128; o > 0; o >>= 1) {
        if (tid < o) sdata[tid] += sdata[tid + o];
        __syncthreads();
    }
    if (tid == 0) bsum[bi] = sdata[0];
}
__global__ void small_both(int nb_g, int nb_d) {
    __shared__ int s[64];
    int tid = threadIdx.x;
    int* bs = (blockIdx.x == 0) ? g_bs_g : g_bs_d;
    int nb = (blockIdx.x == 0) ? nb_g : nb_d;
    int orig = (tid < nb) ? bs[tid] : 0;
    s[tid] = orig;
    __syncthreads();
    for (int o = 1; o < 64; o <<= 1) {
        int v = (tid >= o) ? s[tid - o] : 0;
        __syncthreads();
        s[tid] += v;
        __syncthreads();
    }
    if (tid < nb) bs[tid] = s[tid] - orig;
}
__global__ void fin_both(int nb_g) {
    __shared__ int sh[256];
    int tid = threadIdx.x;
    int *cnt, *row_ptr, *cursor;
    const int* bsums;
    int n, bi;
    if (blockIdx.x < (unsigned)nb_g) {
        cnt = g_cur_g; row_ptr = g_rp_g; cursor = g_cur_g; bsums = g_bs_g; n = NG; bi = blockIdx.x;
    } else {
        cnt = g_cur_d; row_ptr = g_rp_d; cursor = g_cur_d; bsums = g_bs_d; n = ND; bi = blockIdx.x - nb_g;
    }
    int base = bi * 2048 + tid * 8;
    int v[8];
    int tsum = 0;
#pragma unroll
    for (int i = 0; i < 8; i++) {
        int idx = base + i;
        v[i] = (idx < n) ? cnt[idx] : 0;
        tsum += v[i];
    }
    sh[tid] = tsum;
    __syncthreads();
    for (int o = 1; o < 256; o <<= 1) {
        int add = (tid >= o) ? sh[tid - o] : 0;
        __syncthreads();
        sh[tid] += add;
        __syncthreads();
    }
    int run = sh[tid] - tsum + bsums[bi];
#pragma unroll
    for (int i = 0; i < 8; i++) {
        int idx = base + i;
        if (idx < n) {
            cursor[idx] = run;
            run += v[i];
            row_ptr[idx + 1] = run;
        }
    }
    if (bi == 0 && tid == 0) row_ptr[0] = 0;
}
__global__ void scatter_both(const int* __restrict__ src_dg, const int* __restrict__ dst_dg,
                             const int* __restrict__ src_gd, const int* __restrict__ dst_gd,
                             int e) {
    int i = blockIdx.x * blockDim.x + threadIdx.x;
    if (i < e) {
        int p = atomicAdd(&g_cur_g[dst_dg[i]], 1);
        g_col_dg[p] = src_dg[i];
    } else if (i < 2 * e) {
        int j = i - e;
        int p = atomicAdd(&g_cur_d[dst_gd[j]], 1);
        g_col_gd[p] = src_gd[j];
    }
}

// ---------------- fused mean-aggregate (both relations), float4, MLP-2 ----------------
// 16 lanes per node, float4 per lane; out[n] = mean_e a_src[col[e]] + bias + r_self[n]
__global__ void aggregate_both(
    const float* __restrict__ asrc_g, const float* __restrict__ rself_g,
    const float* __restrict__ bias_g, float* __restrict__ out_g,
    const float* __restrict__ asrc_d, const float* __restrict__ rself_d,
    const float* __restrict__ bias_d, float* __restrict__ out_d,
    int gblocks) {
    const float *asrc, *rself, *bias;
    float* out;
    const int *rp, *col;
    int ndst, t;
    if (blockIdx.x < (unsigned)gblocks) {
        asrc = asrc_g; rself = rself_g; bias = bias_g; out = out_g;
        rp = g_rp_g; col = g_col_dg; ndst = NG;
        t = blockIdx.x * 256 + threadIdx.x;
    } else {
        asrc = asrc_d; rself = rself_d; bias = bias_d; out = out_d;
        rp = g_rp_d; col = g_col_gd; ndst = ND;
        t = (blockIdx.x - gblocks) * 256 + threadIdx.x;
    }
    int n = t >> 4;
    int d4 = (t & 15) * 4;
    if (n >= ndst) return;
    int beg = rp[n], end = rp[n + 1];
    float ax = 0.f, ay = 0.f, az = 0.f, aw = 0.f;
    int e = beg;
    for (; e + 2 <= end; e += 2) {
        int c0 = __ldg(&col[e]);
        int c1 = __ldg(&col[e + 1]);
        float4 u = *(const float4*)(asrc + (size_t)c0 * 64 + d4);
        float4 v = *(const float4*)(asrc + (size_t)c1 * 64 + d4);
        ax += u.x + v.x; ay += u.y + v.y; az += u.z + v.z; aw += u.w + v.w;
    }
    if (e < end) {
        int c0 = __ldg(&col[e]);
        float4 u = *(const float4*)(asrc + (size_t)c0 * 64 + d4);
        ax += u.x; ay += u.y; az += u.z; aw += u.w;
    }
    int deg = end - beg;
    float inv = (deg > 0) ? 1.f / (float)deg : 0.f;
    float4 rs = *(const float4*)(rself + (size_t)n * 64 + d4);
    float4 bs = *(const float4*)(bias + d4);
    float4 o;
    o.x = ax * inv + bs.x + rs.x;
    o.y = ay * inv + bs.y + rs.y;
    o.z = az * inv + bs.z + rs.z;
    o.w = aw * inv + bs.w + rs.w;
    *(float4*)(out + (size_t)n * 64 + d4) = o;
}

// ---------------- host launcher ----------------
extern "C" void kernel_launch(void* const* d_in, const int* in_sizes, int n_in,
                              void* d_out, int out_size) {
    const float* x_d = (const float*)d_in[0];
    const float* x_g = (const float*)d_in[1];
    const int* src_dg = (const int*)d_in[2];
    const int* dst_dg = (const int*)d_in[3];
    const int* src_gd = (const int*)d_in[4];
    const int* dst_gd = (const int*)d_in[5];
    const float* Wl1_dg = (const float*)d_in[6];
    const float* bl1_dg = (const float*)d_in[7];
    const float* Wr1_dg = (const float*)d_in[8];
    const float* Wl1_gd = (const float*)d_in[9];
    const float* bl1_gd = (const float*)d_in[10];
    const float* Wr1_gd = (const float*)d_in[11];
    const float* Wl2_dg = (const float*)d_in[12];
    const float* bl2_dg = (const float*)d_in[13];
    const float* Wr2_dg = (const float*)d_in[14];
    const float* Wl2_gd = (const float*)d_in[15];
    const float* bl2_gd = (const float*)d_in[16];
    const float* Wr2_gd = (const float*)d_in[17];
    float* out = (float*)d_out;

    int E = in_sizes[2];
    if (E > NE) E = NE;

    float *ad, *rd, *ag, *rg, *d1, *g1;
    cudaGetSymbolAddress((void**)&ad, g_a_d);
    cudaGetSymbolAddress((void**)&rd, g_r_d);
    cudaGetSymbolAddress((void**)&ag, g_a_g);
    cudaGetSymbolAddress((void**)&rg, g_r_g);
    cudaGetSymbolAddress((void**)&d1, g_d1);
    cudaGetSymbolAddress((void**)&g1, g_g1);

    const int tilesD = (ND + 127) / 128;  // 391
    const int tilesG = (NG + 127) / 128;  // 782
    const int Pd = 100, Pg = 196;         // persistent split (2 CTAs/SM total 296)
    const int smem128 = 2 * 128 * (128 + 8) * 2;  // 69632 (B hi/lo)
    const int smem64 = 2 * 128 * (64 + 8) * 2;    // 36864
    cudaFuncSetAttribute(gemm_mma<128>, cudaFuncAttributeMaxDynamicSharedMemorySize, smem128);
    cudaFuncSetAttribute(gemm_mma<64>, cudaFuncAttributeMaxDynamicSharedMemorySize, smem64);

    const int nb_g = (NG + 2047) / 2048;  // 49
    const int nb_d = (ND + 2047) / 2048;  // 25
    const int gblocks = (NG * 16 + 255) / 256;  // 6250
    const int dblocks = (ND * 16 + 255) / 256;  // 3125

    prep_w_kernel<<<4, 256>>>(Wl1_dg, Wr1_gd, Wl1_gd, Wr1_dg,
                              Wl2_dg, Wr2_gd, Wl2_gd, Wr2_dg);                  // 1
    zero_counts_kernel<<<(NG + 255) / 256, 256>>>();                            // 2
    hist_both<<<(2 * E + 255) / 256, 256>>>(dst_dg, dst_gd, E);                 // 3
    gemm_mma<128><<<Pd + Pg, 256, smem128>>>(x_d, x_g, ad, rd, ag, rg,
                                             0, 1, ND, NG, tilesD, tilesG, Pd); // 4 (profiled)
    sbs_both<<<nb_g + nb_d, 256>>>(nb_g);                                       // 5
    small_both<<<2, 64>>>(nb_g, nb_d);                                          // 6
    fin_both<<<nb_g + nb_d, 256>>>(nb_g);                                       // 7
    scatter_both<<<(2 * E + 255) / 256, 256>>>(src_dg, dst_dg, src_gd, dst_gd, E); // 8

    aggregate_both<<<gblocks + dblocks, 256>>>(ad, rg, bl1_dg, g1,
                                               ag, rd, bl1_gd, d1, gblocks);    // 9

    gemm_mma<64><<<Pd + Pg, 256, smem64>>>(d1, g1, ad, rd, ag, rg,
                                           2, 3, ND, NG, tilesD, tilesG, Pd);   // 10

    aggregate_both<<<gblocks + dblocks, 256>>>(ad, rg, bl2_dg, out + (size_t)ND * 64,
                                               ag, rd, bl2_gd, out, gblocks);   // 11
}

// round 7
// speedup vs baseline: 2.2205x; 1.1291x over previous
#include <cuda_runtime.h>
#include <cuda_bf16.h>
#include <cstdint>

#define ND 50000
#define NG 100000
#define NE 600000

// ---------------- static scratch ----------------
__device__ __align__(16) float g_a_d[(size_t)ND * 64];
__device__ __align__(16) float g_r_d[(size_t)ND * 64];
__device__ __align__(16) float g_a_g[(size_t)NG * 64];
__device__ __align__(16) float g_r_g[(size_t)NG * 64];
__device__ __align__(16) float g_d1[(size_t)ND * 64];
__device__ __align__(16) float g_g1[(size_t)NG * 64];
// 4 weight images: [n=128][k=K] bf16, padded rows (K+8), hi then lo. slot = 69632 B
// k-rows stored PERMUTED: physical pos p holds logical k = blk*16 + 4t + (p&1) + 2*bit3
__device__ __align__(16) char g_wimg[4 * 69632];

__device__ int g_rp_g[NG + 1];
__device__ int g_rp_d[ND + 1];
__device__ int g_cur_g[NG];
__device__ int g_cur_d[ND];
__device__ int g_col_dg[NE];
__device__ int g_col_gd[NE];
__device__ int g_bs_g[64];
__device__ int g_bs_d[64];

// ---------------- helpers ----------------
__device__ __forceinline__ uint32_t smem_u32(const void* p) {
    uint32_t a;
    asm("{ .reg .u64 t; cvta.to.shared.u64 t, %1; cvt.u32.u64 %0, t; }" : "=r"(a) : "l"(p));
    return a;
}
__device__ __forceinline__ void ldm4(uint32_t* r, uint32_t addr) {
    asm volatile("ldmatrix.sync.aligned.m8n8.x4.shared.b16 {%0,%1,%2,%3}, [%4];"
                 : "=r"(r[0]), "=r"(r[1]), "=r"(r[2]), "=r"(r[3]) : "r"(addr));
}
__device__ __forceinline__ void mma_bf16(float* c, const uint32_t* a, const uint32_t* b) {
    asm volatile(
        "mma.sync.aligned.m16n8k16.row.col.f32.bf16.bf16.f32 "
        "{%0,%1,%2,%3}, {%4,%5,%6,%7}, {%8,%9}, {%0,%1,%2,%3};"
        : "+f"(c[0]), "+f"(c[1]), "+f"(c[2]), "+f"(c[3])
        : "r"(a[0]), "r"(a[1]), "r"(a[2]), "r"(a[3]), "r"(b[0]), "r"(b[1]));
}
__device__ __forceinline__ uint32_t bsplit(float x, float y, uint32_t& lo) {
    __nv_bfloat16 hx = __float2bfloat16(x), hy = __float2bfloat16(y);
    __nv_bfloat16 lx = __float2bfloat16(x - __bfloat162float(hx));
    __nv_bfloat16 ly = __float2bfloat16(y - __bfloat162float(hy));
    lo = (uint32_t)__bfloat16_as_ushort(lx) | ((uint32_t)__bfloat16_as_ushort(ly) << 16);
    return (uint32_t)__bfloat16_as_ushort(hx) | ((uint32_t)__bfloat16_as_ushort(hy) << 16);
}

// ---------------- weight image prep (k-permuted) ----------------
// A-side reads float4 at physical k=4t, feeding MMA slots (2t,2t+1,2t+8,2t+9).
// So B image physical position p (within each 16-block) must hold logical
// k = blk*16 + 4*((p>>1)&3) + (p&1) + 2*((p>>3)&1).
__global__ void prep_w_kernel(const float* __restrict__ Wa0, const float* __restrict__ Wb0,
                              const float* __restrict__ Wa1, const float* __restrict__ Wb1,
                              const float* __restrict__ Wa2, const float* __restrict__ Wb2,
                              const float* __restrict__ Wa3, const float* __restrict__ Wb3) {
    int img = blockIdx.x;
    const float *Wa, *Wb;
    int K;
    if (img == 0) { Wa = Wa0; Wb = Wb0; K = 128; }
    else if (img == 1) { Wa = Wa1; Wb = Wb1; K = 128; }
    else if (img == 2) { Wa = Wa2; Wb = Wb2; K = 64; }
    else { Wa = Wa3; Wb = Wb3; K = 64; }
    int rowb = (K + 8) * 2;
    char* hi_img = g_wimg + (size_t)img * 69632;
    char* lo_img = hi_img + 128 * rowb;
    for (int i = threadIdx.x; i < 128 * K; i += blockDim.x) {
        int n = i / K, p = i % K;
        int blk = p >> 4, pi = p & 15;
        int lk = (blk << 4) + 4 * ((pi >> 1) & 3) + (pi & 1) + 2 * ((pi >> 3) & 1);
        float w = (n < 64) ? Wa[lk * 64 + n] : Wb[lk * 64 + (n - 64)];
        __nv_bfloat16 h = __float2bfloat16(w);
        __nv_bfloat16 l = __float2bfloat16(w - __bfloat162float(h));
        *(__nv_bfloat16*)(hi_img + n * rowb + p * 2) = h;
        *(__nv_bfloat16*)(lo_img + n * rowb + p * 2) = l;
    }
}

// ---------------- persistent HMMA GEMM: [a|r](N,64+64) = X[N,K] @ W -------------
// 8 warps = 4m x 2n, CTA tile M=128. B (hi/lo) resident in smem; A streamed as
// float4 (k-permuted), bf16 hi/lo split in regs. Direct register->global epilogue.
template <int K>
__global__ __launch_bounds__(256, 2) void gemm_mma(
    const float* __restrict__ Xd, const float* __restrict__ Xg,
    float* __restrict__ ad, float* __restrict__ rd,
    float* __restrict__ ag, float* __restrict__ rg,
    int img_d, int img_g, int Ndis, int Ngen,
    int tilesD, int tilesG, int Pd) {
    constexpr int STR = K + 8;
    constexpr int ROWB = STR * 2;
    constexpr int BMAT = 128 * ROWB;
    constexpr int NSTEP = K / 16;
    extern __shared__ __align__(16) char smem[];   // B hi then lo

    const float* X;
    float *outa, *outr;
    int Nrows, img, tbeg, tnum, tstep;
    if ((int)blockIdx.x < Pd) {
        X = Xd; outa = ad; outr = rd; Nrows = Ndis; img = img_d;
        tbeg = blockIdx.x; tnum = tilesD; tstep = Pd;
    } else {
        X = Xg; outa = ag; outr = rg; Nrows = Ngen; img = img_g;
        tbeg = blockIdx.x - Pd; tnum = tilesG; tstep = gridDim.x - Pd;
    }

    // load B hi/lo once
    {
        const char* im = g_wimg + (size_t)img * 69632;
        for (int v = threadIdx.x; v < (2 * BMAT) / 16; v += 256)
            ((float4*)smem)[v] = ((const float4*)im)[v];
    }
    __syncthreads();

    const int w = threadIdx.x >> 5, lane = threadIdx.x & 31;
    const int mw = w >> 1, nw = w & 1;
    const int g = lane >> 2, t = lane & 3;
    const uint32_t bB = smem_u32(smem) +
                        (uint32_t)((nw * 64 + ((lane >> 4) << 3) + (lane & 7)) * ROWB +
                                   ((lane >> 3) & 1) * 16);
    float* const o = (nw == 0) ? outa : outr;

    for (int tb = tbeg; tb < tnum; tb += tstep) {
        const int rbase = tb * 128 + mw * 32 + g;
        const int r00 = rbase, r01 = rbase + 8;        // mt=0
        const int r10 = rbase + 16, r11 = rbase + 24;  // mt=1
        const bool v00 = r00 < Nrows, v01 = r01 < Nrows;
        const bool v10 = r10 < Nrows, v11 = r11 < Nrows;
        const float* x00 = X + (size_t)r00 * K + 4 * t;
        const float* x01 = X + (size_t)r01 * K + 4 * t;
        const float* x10 = X + (size_t)r10 * K + 4 * t;
        const float* x11 = X + (size_t)r11 * K + 4 * t;

        float c[2][8][4];
#pragma unroll
        for (int mt = 0; mt < 2; mt++)
#pragma unroll
            for (int j = 0; j < 8; j++)
#pragma unroll
                for (int q = 0; q < 4; q++) c[mt][j][q] = 0.f;

#pragma unroll
        for (int s = 0; s < NSTEP; s++) {
            const int ke = s * 16;
            const float4 z4 = make_float4(0.f, 0.f, 0.f, 0.f);
            float4 q00 = v00 ? *(const float4*)(x00 + ke) : z4;
            float4 q01 = v01 ? *(const float4*)(x01 + ke) : z4;
            float4 q10 = v10 ? *(const float4*)(x10 + ke) : z4;
            float4 q11 = v11 ? *(const float4*)(x11 + ke) : z4;
            uint32_t ah0[4], al0[4], ah1[4], al1[4];
            ah0[0] = bsplit(q00.x, q00.y, al0[0]);   // row g,   k 2t,2t+1
            ah0[2] = bsplit(q00.z, q00.w, al0[2]);   // row g,   k 2t+8,2t+9
            ah0[1] = bsplit(q01.x, q01.y, al0[1]);   // row g+8
            ah0[3] = bsplit(q01.z, q01.w, al0[3]);
            ah1[0] = bsplit(q10.x, q10.y, al1[0]);
            ah1[2] = bsplit(q10.z, q10.w, al1[2]);
            ah1[1] = bsplit(q11.x, q11.y, al1[1]);
            ah1[3] = bsplit(q11.z, q11.w, al1[3]);
            const uint32_t ko = (uint32_t)(s * 32);
#pragma unroll
            for (int p = 0; p < 4; p++) {
                uint32_t bh[4], bl[4];
                ldm4(bh, bB + p * 16 * ROWB + ko);
                ldm4(bl, bB + BMAT + p * 16 * ROWB + ko);
#pragma unroll
                for (int q = 0; q < 2; q++) {
                    int j = 2 * p + q;
                    mma_bf16(c[0][j], ah0, bh + 2 * q);
                    mma_bf16(c[0][j], ah0, bl + 2 * q);
                    mma_bf16(c[0][j], al0, bh + 2 * q);
                    mma_bf16(c[1][j], ah1, bh + 2 * q);
                    mma_bf16(c[1][j], ah1, bl + 2 * q);
                    mma_bf16(c[1][j], al1, bh + 2 * q);
                }
            }
        }

        // direct epilogue: nw=0 warps own cols 0..63 (a), nw=1 own 64..127 (r)
#pragma unroll
        for (int mt = 0; mt < 2; mt++) {
            const int ra = rbase + mt * 16;
            const int rb = ra + 8;
            const bool va = (mt == 0) ? v00 : v10;
            const bool vb = (mt == 0) ? v01 : v11;
#pragma unroll
            for (int j = 0; j < 8; j++) {
                int col = j * 8 + 2 * t;
                if (va) *(float2*)(o + (size_t)ra * 64 + col) = make_float2(c[mt][j][0], c[mt][j][1]);
                if (vb) *(float2*)(o + (size_t)rb * 64 + col) = make_float2(c[mt][j][2], c[mt][j][3]);
            }
        }
    }
}

// ---------------- CSR build (fused across both relations) ----------------
__global__ void zero_counts_kernel() {
    int i = blockIdx.x * blockDim.x + threadIdx.x;
    if (i < NG) g_cur_g[i] = 0;
    if (i < ND) g_cur_d[i] = 0;
}
__global__ void hist_both(const int* __restrict__ dst_dg, const int* __restrict__ dst_gd, int e) {
    int i = blockIdx.x * blockDim.x + threadIdx.x;
    if (i < e) atomicAdd(&g_cur_g[dst_dg[i]], 1);
    else if (i < 2 * e) atomicAdd(&g_cur_d[dst_gd[i - e]], 1);
}
__global__ void sbs_both(int nb_g) {
    __shared__ int sdata[256];
    int tid = threadIdx.x;
    const int* cnt;
    int n, bi;
    int* bsum;
    if (blockIdx.x < (unsigned)nb_g) { cnt = g_cur_g; n = NG; bi = blockIdx.x; bsum = g_bs_g; }
    else { cnt = g_cur_d; n = ND; bi = blockIdx.x - nb_g; bsum = g_bs_d; }
    int base = bi * 2048;
    int s = 0;
    for (int i = tid; i < 2048; i += 256) {
        int idx = base + i;
        if (idx < n) s += cnt[idx];
    }
    sdata[tid] = s;
    __syncthreads();
    for (int o = 128; o > 0; o >>= 1) {
        if (tid < o) sdata[tid] += sdata[tid + o];
        __syncthreads();
    }
    if (tid == 0) bsum[bi] = sdata[0];
}
__global__ void small_both(int nb_g, int nb_d) {
    __shared__ int s[64];
    int tid = threadIdx.x;
    int* bs = (blockIdx.x == 0) ? g_bs_g : g_bs_d;
    int nb = (blockIdx.x == 0) ? nb_g : nb_d;
    int orig = (tid < nb) ? bs[tid] : 0;
    s[tid] = orig;
    __syncthreads();
    for (int o = 1; o < 64; o <<= 1) {
        int v = (tid >= o) ? s[tid - o] : 0;
        __syncthreads();
        s[tid] += v;
        __syncthreads();
    }
    if (tid < nb) bs[tid] = s[tid] - orig;
}
__global__ void fin_both(int nb_g) {
    __shared__ int sh[256];
    int tid = threadIdx.x;
    int *cnt, *row_ptr, *cursor;
    const int* bsums;
    int n, bi;
    if (blockIdx.x < (unsigned)nb_g) {
        cnt = g_cur_g; row_ptr = g_rp_g; cursor = g_cur_g; bsums = g_bs_g; n = NG; bi = blockIdx.x;
    } else {
        cnt = g_cur_d; row_ptr = g_rp_d; cursor = g_cur_d; bsums = g_bs_d; n = ND; bi = blockIdx.x - nb_g;
    }
    int base = bi * 2048 + tid * 8;
    int v[8];
    int tsum = 0;
#pragma unroll
    for (int i = 0; i < 8; i++) {
        int idx = base + i;
        v[i] = (idx < n) ? cnt[idx] : 0;
        tsum += v[i];
    }
    sh[tid] = tsum;
    __syncthreads();
    for (int o = 1; o < 256; o <<= 1) {
        int add = (tid >= o) ? sh[tid - o] : 0;
        __syncthreads();
        sh[tid] += add;
        __syncthreads();
    }
    int run = sh[tid] - tsum + bsums[bi];
#pragma unroll
    for (int i = 0; i < 8; i++) {
        int idx = base + i;
        if (idx < n) {
            cursor[idx] = run;
            run += v[i];
            row_ptr[idx + 1] = run;
        }
    }
    if (bi == 0 && tid == 0) row_ptr[0] = 0;
}
__global__ void scatter_both(const int* __restrict__ src_dg, const int* __restrict__ dst_dg,
                             const int* __restrict__ src_gd, const int* __restrict__ dst_gd,
                             int e) {
    int i = blockIdx.x * blockDim.x + threadIdx.x;
    if (i < e) {
        int p = atomicAdd(&g_cur_g[dst_dg[i]], 1);
        g_col_dg[p] = src_dg[i];
    } else if (i < 2 * e) {
        int j = i - e;
        int p = atomicAdd(&g_cur_d[dst_gd[j]], 1);
        g_col_gd[p] = src_gd[j];
    }
}

// ---------------- fused mean-aggregate (both relations), float4, MLP-4 ----------------
__global__ void aggregate_both(
    const float* __restrict__ asrc_g, const float* __restrict__ rself_g,
    const float* __restrict__ bias_g, float* __restrict__ out_g,
    const float* __restrict__ asrc_d, const float* __restrict__ rself_d,
    const float* __restrict__ bias_d, float* __restrict__ out_d,
    int gblocks) {
    const float *asrc, *rself, *bias;
    float* out;
    const int *rp, *col;
    int ndst, t;
    if (blockIdx.x < (unsigned)gblocks) {
        asrc = asrc_g; rself = rself_g; bias = bias_g; out = out_g;
        rp = g_rp_g; col = g_col_dg; ndst = NG;
        t = blockIdx.x * 256 + threadIdx.x;
    } else {
        asrc = asrc_d; rself = rself_d; bias = bias_d; out = out_d;
        rp = g_rp_d; col = g_col_gd; ndst = ND;
        t = (blockIdx.x - gblocks) * 256 + threadIdx.x;
    }
    int n = t >> 4;
    int d4 = (t & 15) * 4;
    if (n >= ndst) return;
    int beg = rp[n], end = rp[n + 1];
    float ax = 0.f, ay = 0.f, az = 0.f, aw = 0.f;
    int e = beg;
    for (; e + 4 <= end; e += 4) {
        int c0 = __ldg(&col[e]);
        int c1 = __ldg(&col[e + 1]);
        int c2 = __ldg(&col[e + 2]);
        int c3 = __ldg(&col[e + 3]);
        float4 u0 = *(const float4*)(asrc + (size_t)c0 * 64 + d4);
        float4 u1 = *(const float4*)(asrc + (size_t)c1 * 64 + d4);
        float4 u2 = *(const float4*)(asrc + (size_t)c2 * 64 + d4);
        float4 u3 = *(const float4*)(asrc + (size_t)c3 * 64 + d4);
        ax += (u0.x + u1.x) + (u2.x + u3.x);
        ay += (u0.y + u1.y) + (u2.y + u3.y);
        az += (u0.z + u1.z) + (u2.z + u3.z);
        aw += (u0.w + u1.w) + (u2.w + u3.w);
    }
    for (; e < end; e++) {
        int c0 = __ldg(&col[e]);
        float4 u = *(const float4*)(asrc + (size_t)c0 * 64 + d4);
        ax += u.x; ay += u.y; az += u.z; aw += u.w;
    }
    int deg = end - beg;
    float inv = (deg > 0) ? 1.f / (float)deg : 0.f;
    float4 rs = *(const float4*)(rself + (size_t)n * 64 + d4);
    float4 bs = *(const float4*)(bias + d4);
    float4 o;
    o.x = ax * inv + bs.x + rs.x;
    o.y = ay * inv + bs.y + rs.y;
    o.z = az * inv + bs.z + rs.z;
    o.w = aw * inv + bs.w + rs.w;
    *(float4*)(out + (size_t)n * 64 + d4) = o;
}

// ---------------- host launcher ----------------
extern "C" void kernel_launch(void* const* d_in, const int* in_sizes, int n_in,
                              void* d_out, int out_size) {
    const float* x_d = (const float*)d_in[0];
    const float* x_g = (const float*)d_in[1];
    const int* src_dg = (const int*)d_in[2];
    const int* dst_dg = (const int*)d_in[3];
    const int* src_gd = (const int*)d_in[4];
    const int* dst_gd = (const int*)d_in[5];
    const float* Wl1_dg = (const float*)d_in[6];
    const float* bl1_dg = (const float*)d_in[7];
    const float* Wr1_dg = (const float*)d_in[8];
    const float* Wl1_gd = (const float*)d_in[9];
    const float* bl1_gd = (const float*)d_in[10];
    const float* Wr1_gd = (const float*)d_in[11];
    const float* Wl2_dg = (const float*)d_in[12];
    const float* bl2_dg = (const float*)d_in[13];
    const float* Wr2_dg = (const float*)d_in[14];
    const float* Wl2_gd = (const float*)d_in[15];
    const float* bl2_gd = (const float*)d_in[16];
    const float* Wr2_gd = (const float*)d_in[17];
    float* out = (float*)d_out;

    int E = in_sizes[2];
    if (E > NE) E = NE;

    float *ad, *rd, *ag, *rg, *d1, *g1;
    cudaGetSymbolAddress((void**)&ad, g_a_d);
    cudaGetSymbolAddress((void**)&rd, g_r_d);
    cudaGetSymbolAddress((void**)&ag, g_a_g);
    cudaGetSymbolAddress((void**)&rg, g_r_g);
    cudaGetSymbolAddress((void**)&d1, g_d1);
    cudaGetSymbolAddress((void**)&g1, g_g1);

    const int tilesD = (ND + 127) / 128;  // 391
    const int tilesG = (NG + 127) / 128;  // 782
    const int Pd = 100, Pg = 196;         // persistent split (2 CTAs/SM total 296)
    const int smem128 = 2 * 128 * (128 + 8) * 2;  // 69632 (B hi/lo)
    const int smem64 = 2 * 128 * (64 + 8) * 2;    // 36864
    cudaFuncSetAttribute(gemm_mma<128>, cudaFuncAttributeMaxDynamicSharedMemorySize, smem128);
    cudaFuncSetAttribute(gemm_mma<64>, cudaFuncAttributeMaxDynamicSharedMemorySize, smem64);

    const int nb_g = (NG + 2047) / 2048;  // 49
    const int nb_d = (ND + 2047) / 2048;  // 25
    const int gblocks = (NG * 16 + 255) / 256;  // 6250
    const int dblocks = (ND * 16 + 255) / 256;  // 3125

    // fork a side stream so the CSR chain overlaps the layer-1 GEMM
    cudaStream_t s2;
    cudaStreamCreateWithFlags(&s2, cudaStreamNonBlocking);
    cudaEvent_t eFork, eJoin;
    cudaEventCreateWithFlags(&eFork, cudaEventDisableTiming);
    cudaEventCreateWithFlags(&eJoin, cudaEventDisableTiming);

    prep_w_kernel<<<4, 256>>>(Wl1_dg, Wr1_gd, Wl1_gd, Wr1_dg,
                              Wl2_dg, Wr2_gd, Wl2_gd, Wr2_dg);
    cudaEventRecord(eFork, 0);
    cudaStreamWaitEvent(s2, eFork, 0);

    // side stream: CSR build
    zero_counts_kernel<<<(NG + 255) / 256, 256, 0, s2>>>();
    hist_both<<<(2 * E + 255) / 256, 256, 0, s2>>>(dst_dg, dst_gd, E);
    sbs_both<<<nb_g + nb_d, 256, 0, s2>>>(nb_g);
    small_both<<<2, 64, 0, s2>>>(nb_g, nb_d);
    fin_both<<<nb_g + nb_d, 256, 0, s2>>>(nb_g);
    scatter_both<<<(2 * E + 255) / 256, 256, 0, s2>>>(src_dg, dst_dg, src_gd, dst_gd, E);
    cudaEventRecord(eJoin, s2);

    // main stream: layer-1 GEMM (concurrent with CSR chain)
    gemm_mma<128><<<Pd + Pg, 256, smem128>>>(x_d, x_g, ad, rd, ag, rg,
                                             0, 1, ND, NG, tilesD, tilesG, Pd);
    cudaStreamWaitEvent(0, eJoin, 0);   // join

    aggregate_both<<<gblocks + dblocks, 256>>>(ad, rg, bl1_dg, g1,
                                               ag, rd, bl1_gd, d1, gblocks);

    gemm_mma<64><<<Pd + Pg, 256, smem64>>>(d1, g1, ad, rd, ag, rg,
                                           2, 3, ND, NG, tilesD, tilesG, Pd);

    aggregate_both<<<gblocks + dblocks, 256>>>(ad, rg, bl2_dg, out + (size_t)ND * 64,
                                               ag, rd, bl2_gd, out, gblocks);

    cudaStreamDestroy(s2);
    cudaEventDestroy(eFork);
    cudaEventDestroy(eJoin);
}